// round 11
// baseline (speedup 1.0000x reference)
#include <cuda_runtime.h>
#include <cuda_bf16.h>
#include <cuda_fp16.h>
#include <math.h>

#define Nn 50000
#define Ee 800000
#define Pp 2
#define Hh 4
#define Ff 32
#define HF 128
#define INF 128
#define TOT (Pp * Nn)          // 100000 destination slots
#define SCAN_B 98              // ceil(TOT/1024)
#define PE ((size_t)Pp * Ee)   // total CSR positions

// ---- scratch (device globals; allocation-free) ----
__device__ __half g_feat_h[(size_t)Pp * Nn * HF]; // 25.6 MB (gather path)
__device__ float g_el[(size_t)Pp * Nn * Hh];
__device__ float g_er[(size_t)Pp * Nn * Hh];
__device__ float g_out[(size_t)Pp * Nn * HF];    // 51.2 MB
__device__ float g_wsum[Pp];
__device__ int   g_deg[TOT];
__device__ int   g_off[TOT];
__device__ int   g_cur[TOT];
__device__ int   g_bsum[SCAN_B];
__device__ int   g_csr_src[(size_t)Pp * Ee + 32];   // src ids, CSR order
__device__ int   g_csr_dst[(size_t)Pp * Ee + 32];   // dst ids, CSR order
__device__ float g_csr_w[Hh * PE + 32];             // weights: 4 head planes

// ---- packed fp32x2 helpers (Blackwell) ----
__device__ __forceinline__ unsigned long long pack2(float a, float b) {
    unsigned long long r;
    asm("mov.b64 %0, {%1, %2};" : "=l"(r) : "f"(a), "f"(b));
    return r;
}
__device__ __forceinline__ void unpack2(unsigned long long v, float& a, float& b) {
    asm("mov.b64 {%0, %1}, %2;" : "=f"(a), "=f"(b) : "l"(v));
}
__device__ __forceinline__ unsigned long long fma2(unsigned long long a,
                                                   unsigned long long b,
                                                   unsigned long long c) {
    unsigned long long r;
    asm("fma.rn.f32x2 %0, %1, %2, %3;" : "=l"(r) : "l"(a), "l"(b), "l"(c));
    return r;
}

// ============================================================
// K1: feat = h @ W_p (stored fp16) ; el/er attn dots (fp32)
// warp = 8 nodes, lane = 4 consecutive cols
// ============================================================
__global__ void __launch_bounds__(256) feat_kernel(
                            const float* __restrict__ h,
                            const float* __restrict__ fc_w,
                            const float* __restrict__ attn_l,
                            const float* __restrict__ attn_r) {
    int p = blockIdx.y;
    const ulonglong2* W2 = (const ulonglong2*)(fc_w + (size_t)p * INF * HF);
    int warpId = threadIdx.x >> 5;
    int lane = threadIdx.x & 31;
    int gw = blockIdx.x * 8 + warpId;
    int n0 = gw * 8;                    // Nn % 8 == 0
    if (n0 >= Nn) return;

    const float4* h4 = (const float4*)h;

    unsigned long long acc[8][2];
    #pragma unroll
    for (int r = 0; r < 8; r++) { acc[r][0] = 0ull; acc[r][1] = 0ull; }

    for (int k4 = 0; k4 < 32; k4++) {
        float4 hv0 = __ldg(h4 + (size_t)(n0 + 0) * 32 + k4);
        float4 hv1 = __ldg(h4 + (size_t)(n0 + 1) * 32 + k4);
        float4 hv2 = __ldg(h4 + (size_t)(n0 + 2) * 32 + k4);
        float4 hv3 = __ldg(h4 + (size_t)(n0 + 3) * 32 + k4);
        float4 hv4 = __ldg(h4 + (size_t)(n0 + 4) * 32 + k4);
        float4 hv5 = __ldg(h4 + (size_t)(n0 + 5) * 32 + k4);
        float4 hv6 = __ldg(h4 + (size_t)(n0 + 6) * 32 + k4);
        float4 hv7 = __ldg(h4 + (size_t)(n0 + 7) * 32 + k4);
        float hs[8][4] = {
            {hv0.x, hv0.y, hv0.z, hv0.w}, {hv1.x, hv1.y, hv1.z, hv1.w},
            {hv2.x, hv2.y, hv2.z, hv2.w}, {hv3.x, hv3.y, hv3.z, hv3.w},
            {hv4.x, hv4.y, hv4.z, hv4.w}, {hv5.x, hv5.y, hv5.z, hv5.w},
            {hv6.x, hv6.y, hv6.z, hv6.w}, {hv7.x, hv7.y, hv7.z, hv7.w}};
        #pragma unroll
        for (int kk = 0; kk < 4; kk++) {
            ulonglong2 wv = W2[(size_t)(k4 * 4 + kk) * 32 + lane];
            #pragma unroll
            for (int r = 0; r < 8; r++) {
                unsigned long long pr = pack2(hs[r][kk], hs[r][kk]);
                acc[r][0] = fma2(pr, wv.x, acc[r][0]);
                acc[r][1] = fma2(pr, wv.y, acc[r][1]);
            }
        }
    }

    float4 accs[8];
    #pragma unroll
    for (int r = 0; r < 8; r++) {
        unpack2(acc[r][0], accs[r].x, accs[r].y);
        unpack2(acc[r][1], accs[r].z, accs[r].w);
    }

    uint2* feath = (uint2*)g_feat_h;
    #pragma unroll
    for (int r = 0; r < 8; r++) {
        __half2 a01 = __floats2half2_rn(accs[r].x, accs[r].y);
        __half2 a23 = __floats2half2_rn(accs[r].z, accs[r].w);
        uint2 st;
        st.x = *reinterpret_cast<unsigned int*>(&a01);
        st.y = *reinterpret_cast<unsigned int*>(&a23);
        feath[((size_t)p * Nn + n0 + r) * 32 + lane] = st;
    }

    float4 al4 = ((const float4*)(attn_l + (size_t)p * HF))[lane];
    float4 ar4 = ((const float4*)(attn_r + (size_t)p * HF))[lane];
    int head = lane >> 3;

    #pragma unroll
    for (int j = 0; j < 8; j++) {
        float pl = accs[j].x * al4.x + accs[j].y * al4.y + accs[j].z * al4.z + accs[j].w * al4.w;
        float pr = accs[j].x * ar4.x + accs[j].y * ar4.y + accs[j].z * ar4.z + accs[j].w * ar4.w;
        #pragma unroll
        for (int off = 4; off >= 1; off >>= 1) {
            pl += __shfl_xor_sync(0xffffffffu, pl, off);
            pr += __shfl_xor_sync(0xffffffffu, pr, off);
        }
        if ((lane & 7) == 0) {
            g_el[((size_t)p * Nn + n0 + j) * Hh + head] = pl;
            g_er[((size_t)p * Nn + n0 + j) * Hh + head] = pr;
        }
    }
}

// ============================================================
// CSR build: histogram -> scan -> scatter (src + dst ids)
// ============================================================
__global__ void hist_kernel(const int* __restrict__ dst) {
    int p = blockIdx.y;
    int e = blockIdx.x * 256 + threadIdx.x;
    if (e >= Ee) return;
    atomicAdd(&g_deg[p * Nn + __ldg(dst + (size_t)p * Ee + e)], 1);
}

__global__ void scan1_kernel() {
    __shared__ int wsum[32];
    int tid = threadIdx.x, lane = tid & 31, wid = tid >> 5;
    int i = blockIdx.x * 1024 + tid;
    int v = (i < TOT) ? g_deg[i] : 0;
    int x = v;
    #pragma unroll
    for (int o = 1; o < 32; o <<= 1) {
        int y = __shfl_up_sync(0xffffffffu, x, o);
        if (lane >= o) x += y;
    }
    if (lane == 31) wsum[wid] = x;
    __syncthreads();
    if (wid == 0) {
        int s = wsum[lane];
        #pragma unroll
        for (int o = 1; o < 32; o <<= 1) {
            int y = __shfl_up_sync(0xffffffffu, s, o);
            if (lane >= o) s += y;
        }
        wsum[lane] = s;
    }
    __syncthreads();
    int woff = (wid == 0) ? 0 : wsum[wid - 1];
    if (i < TOT) g_off[i] = woff + x - v;
    if (tid == 1023) g_bsum[blockIdx.x] = wsum[31];
}

__global__ void scan23_kernel() {
    __shared__ int sh_scan[SCAN_B];
    if (threadIdx.x < 32) {
        int lane = threadIdx.x;
        int v[4];
        int s = 0;
        #pragma unroll
        for (int j = 0; j < 4; j++) {
            int idx = lane * 4 + j;
            int t = (idx < SCAN_B) ? g_bsum[idx] : 0;
            v[j] = s;
            s += t;
        }
        int x = s;
        #pragma unroll
        for (int o = 1; o < 32; o <<= 1) {
            int y = __shfl_up_sync(0xffffffffu, x, o);
            if (lane >= o) x += y;
        }
        int excl = x - s;
        #pragma unroll
        for (int j = 0; j < 4; j++) {
            int idx = lane * 4 + j;
            if (idx < SCAN_B) sh_scan[idx] = excl + v[j];
        }
    }
    __syncthreads();
    int i = blockIdx.x * 1024 + threadIdx.x;
    if (i < TOT) {
        int o = g_off[i] + sh_scan[blockIdx.x];
        g_off[i] = o;
        g_cur[i] = o;
    }
}

__global__ void scatter_kernel(const int* __restrict__ src,
                               const int* __restrict__ dst) {
    int p = blockIdx.y;
    int e = blockIdx.x * 256 + threadIdx.x;
    if (e >= Ee) return;
    size_t idx = (size_t)p * Ee + e;
    int d = __ldg(dst + idx);
    int pos = atomicAdd(&g_cur[p * Nn + d], 1);
    g_csr_src[pos] = __ldg(src + idx);
    g_csr_dst[pos] = d;
}

// ============================================================
// weight pass: edge-parallel over CSR positions; gathers el/er
// (random, MLP-unbounded) and writes 4 head planes COALESCED.
// Positions [0,Ee) belong to metapath 0, [Ee,2Ee) to metapath 1.
// ============================================================
__global__ void weight_kernel() {
    size_t i = (size_t)blockIdx.x * 256 + threadIdx.x;
    if (i >= PE) return;
    int p = (i >= (size_t)Ee) ? 1 : 0;
    size_t pbase = (size_t)p * Nn;
    int s = g_csr_src[i];
    int d = g_csr_dst[i];
    float4 a = ((const float4*)g_el)[pbase + s];
    float4 b = ((const float4*)g_er)[pbase + d];
    float v0 = a.x + b.x; v0 = v0 > 0.f ? v0 : 0.2f * v0;
    float v1 = a.y + b.y; v1 = v1 > 0.f ? v1 : 0.2f * v1;
    float v2 = a.z + b.z; v2 = v2 > 0.f ? v2 : 0.2f * v2;
    float v3 = a.w + b.w; v3 = v3 > 0.f ? v3 : 0.2f * v3;
    g_csr_w[0 * PE + i] = __expf(v0);
    g_csr_w[1 * PE + i] = __expf(v1);
    g_csr_w[2 * PE + i] = __expf(v2);
    g_csr_w[3 * PE + i] = __expf(v3);
}

// ============================================================
// K4: CSR aggregation — warp per dst node, direct LDG.
// Weights preloaded coalesced from head planes (no dependency);
// feat rows gathered 8-at-a-time (independent LDG.64s).
// No smem -> high occupancy.
// ============================================================
__global__ void __launch_bounds__(256) agg_kernel() {
    int w = blockIdx.x * 8 + (threadIdx.x >> 5);
    if (w >= TOT) return;
    int lane = threadIdx.x & 31;
    int p = (w >= Nn) ? 1 : 0;
    size_t pbase = (size_t)p * Nn;

    int beg = g_off[w];
    int deg = g_deg[w];
    int head = lane >> 3;

    const uint2* feath = (const uint2*)g_feat_h;
    unsigned long long a00 = 0ull, a01 = 0ull;
    unsigned long long a10 = 0ull, a11 = 0ull;
    float den = 0.f;

    for (int j = 0; j < deg; j += 32) {
        int cnt = min(32, deg - j);
        int s = g_csr_src[beg + j + min(lane, cnt - 1)];

        // coalesced weight loads: lane covers edge (q*8+(lane&7)), its head
        float wreg[4];
        #pragma unroll
        for (int q = 0; q < 4; q++) {
            int ek = q * 8 + (lane & 7);
            wreg[q] = g_csr_w[(size_t)head * PE + beg + j + min(ek, cnt - 1)];
        }

        #pragma unroll
        for (int q = 0; q < 4; q++) {
            int kbase = q * 8;
            if (kbase >= cnt) break;
            int m = min(8, cnt - kbase);
            uint2 f[8];
            float wk[8];
            #pragma unroll
            for (int t = 0; t < 8; t++) {
                if (t < m) {
                    int sk = __shfl_sync(0xffffffffu, s, kbase + t);
                    f[t] = __ldg(feath + (pbase + sk) * 32 + lane);
                    wk[t] = __shfl_sync(0xffffffffu, wreg[q], (lane & 24) | t);
                }
            }
            #pragma unroll
            for (int t = 0; t < 8; t++) {
                if (t < m) {
                    float2 fa = __half22float2(*reinterpret_cast<__half2*>(&f[t].x));
                    float2 fb = __half22float2(*reinterpret_cast<__half2*>(&f[t].y));
                    unsigned long long pw = pack2(wk[t], wk[t]);
                    if (t & 1) {
                        a10 = fma2(pw, pack2(fa.x, fa.y), a10);
                        a11 = fma2(pw, pack2(fb.x, fb.y), a11);
                    } else {
                        a00 = fma2(pw, pack2(fa.x, fa.y), a00);
                        a01 = fma2(pw, pack2(fb.x, fb.y), a01);
                    }
                    den += wk[t];
                }
            }
        }
    }

    float ax0, ay0, az0, aw0, ax1, ay1, az1, aw1;
    unpack2(a00, ax0, ay0); unpack2(a01, az0, aw0);
    unpack2(a10, ax1, ay1); unpack2(a11, az1, aw1);
    float inv = 1.0f / fmaxf(den, 1e-9f);
    float4 r;
    r.x = (ax0 + ax1) * inv;
    r.y = (ay0 + ay1) * inv;
    r.z = (az0 + az1) * inv;
    r.w = (aw0 + aw1) * inv;
    ((float4*)g_out)[(size_t)w * 32 + lane] = r;
}

// ============================================================
// K5: semantic attention scores — 8 nodes/warp (halved W1 traffic)
// ============================================================
__global__ void __launch_bounds__(256) sem_kernel(
                           const float* __restrict__ bias,
                           const float* __restrict__ sem_w1,
                           const float* __restrict__ sem_b1,
                           const float* __restrict__ sem_w2) {
    __shared__ __align__(16) float z_sh[64 * HF];   // 32 KB
    int p = blockIdx.y;
    int base = blockIdx.x * 64;

    for (int i = threadIdx.x; i < 64 * HF; i += 256) {
        int node = base + (i >> 7);
        int c = i & 127;
        float z = 0.f;
        if (node < Nn) {
            float raw = g_out[((size_t)p * Nn + node) * HF + c] + bias[(size_t)p * HF + c];
            z = raw > 0.f ? raw : (__expf(raw) - 1.0f);
        }
        z_sh[i] = z;
    }
    __syncthreads();

    int warpId = threadIdx.x >> 5;
    int lane = threadIdx.x & 31;
    const ulonglong2* W2 = (const ulonglong2*)sem_w1;
    const float4* z4 = (const float4*)z_sh;

    unsigned long long acc[8][2];
    #pragma unroll
    for (int r = 0; r < 8; r++) { acc[r][0] = 0ull; acc[r][1] = 0ull; }

    for (int k4 = 0; k4 < 32; k4++) {
        float zs[8][4];
        #pragma unroll
        for (int r = 0; r < 8; r++) {
            float4 zv = z4[(warpId * 8 + r) * 32 + k4];
            zs[r][0] = zv.x; zs[r][1] = zv.y; zs[r][2] = zv.z; zs[r][3] = zv.w;
        }
        #pragma unroll
        for (int kk = 0; kk < 4; kk++) {
            ulonglong2 wv = W2[(size_t)(k4 * 4 + kk) * 32 + lane];
            #pragma unroll
            for (int r = 0; r < 8; r++) {
                unsigned long long pr = pack2(zs[r][kk], zs[r][kk]);
                acc[r][0] = fma2(pr, wv.x, acc[r][0]);
                acc[r][1] = fma2(pr, wv.y, acc[r][1]);
            }
        }
    }

    float4 b14 = ((const float4*)sem_b1)[lane];
    float4 w24 = ((const float4*)sem_w2)[lane];

    float total = 0.f;
    #pragma unroll
    for (int j = 0; j < 8; j++) {
        float4 a;
        unpack2(acc[j][0], a.x, a.y);
        unpack2(acc[j][1], a.z, a.w);
        float cj = tanhf(a.x + b14.x) * w24.x
                 + tanhf(a.y + b14.y) * w24.y
                 + tanhf(a.z + b14.z) * w24.z
                 + tanhf(a.w + b14.w) * w24.w;
        #pragma unroll
        for (int off = 16; off >= 1; off >>= 1)
            cj += __shfl_xor_sync(0xffffffffu, cj, off);
        int node = base + warpId * 8 + j;
        if (node < Nn) total += cj;
    }
    if (lane == 0) atomicAdd(&g_wsum[p], total);
}

// ============================================================
// K6: combine with semantic softmax
// ============================================================
__global__ void final_kernel(const float* __restrict__ bias,
                             float* __restrict__ out) {
    size_t i = (size_t)blockIdx.x * 256 + threadIdx.x;
    if (i >= (size_t)Nn * 32) return;
    float w0 = g_wsum[0] * (1.0f / Nn);
    float w1 = g_wsum[1] * (1.0f / Nn);
    float m = fmaxf(w0, w1);
    float e0 = __expf(w0 - m), e1 = __expf(w1 - m);
    float inv = 1.0f / (e0 + e1);
    float b0 = e0 * inv, b1 = e1 * inv;

    int c4 = (int)(i & 31);
    float4 r0 = ((const float4*)g_out)[i];
    float4 r1 = ((const float4*)g_out)[(size_t)Nn * 32 + i];
    float4 bi0 = ((const float4*)bias)[c4];
    float4 bi1 = ((const float4*)bias)[32 + c4];

    float4 res;
    float v;
    v = r0.x + bi0.x; v = v > 0.f ? v : (__expf(v) - 1.f); res.x = b0 * v;
    v = r0.y + bi0.y; v = v > 0.f ? v : (__expf(v) - 1.f); res.y = b0 * v;
    v = r0.z + bi0.z; v = v > 0.f ? v : (__expf(v) - 1.f); res.z = b0 * v;
    v = r0.w + bi0.w; v = v > 0.f ? v : (__expf(v) - 1.f); res.w = b0 * v;
    v = r1.x + bi1.x; v = v > 0.f ? v : (__expf(v) - 1.f); res.x += b1 * v;
    v = r1.y + bi1.y; v = v > 0.f ? v : (__expf(v) - 1.f); res.y += b1 * v;
    v = r1.z + bi1.z; v = v > 0.f ? v : (__expf(v) - 1.f); res.z += b1 * v;
    v = r1.w + bi1.w; v = v > 0.f ? v : (__expf(v) - 1.f); res.w += b1 * v;

    ((float4*)out)[i] = res;
}

extern "C" void kernel_launch(void* const* d_in, const int* in_sizes, int n_in,
                              void* d_out, int out_size) {
    const float* h      = (const float*)d_in[0];
    const int*   src    = (const int*)  d_in[1];
    const int*   dst    = (const int*)  d_in[2];
    const float* fc_w   = (const float*)d_in[3];
    const float* attn_l = (const float*)d_in[4];
    const float* attn_r = (const float*)d_in[5];
    const float* bias   = (const float*)d_in[6];
    const float* sem_w1 = (const float*)d_in[7];
    const float* sem_b1 = (const float*)d_in[8];
    const float* sem_w2 = (const float*)d_in[9];
    float* out = (float*)d_out;

    static cudaStream_t s2 = nullptr;
    static cudaEvent_t evFork = nullptr, evJoin = nullptr;
    if (s2 == nullptr) {
        cudaStreamCreateWithFlags(&s2, cudaStreamNonBlocking);
        cudaEventCreateWithFlags(&evFork, cudaEventDisableTiming);
        cudaEventCreateWithFlags(&evJoin, cudaEventDisableTiming);
    }

    void *p_deg, *p_wsum;
    cudaGetSymbolAddress(&p_deg, g_deg);
    cudaGetSymbolAddress(&p_wsum, g_wsum);

    // fork: full CSR build (hist+scan+scatter) on s2, feat GEMM on main
    cudaEventRecord(evFork, 0);
    cudaStreamWaitEvent(s2, evFork, 0);

    // --- branch B (s2): histogram + offsets + scatter ---
    cudaMemsetAsync(p_deg, 0, sizeof(int) * TOT, s2);
    dim3 gEdge((Ee + 255) / 256, Pp);
    hist_kernel<<<gEdge, 256, 0, s2>>>(dst);
    scan1_kernel<<<SCAN_B, 1024, 0, s2>>>();
    scan23_kernel<<<SCAN_B, 1024, 0, s2>>>();
    scatter_kernel<<<gEdge, 256, 0, s2>>>(src, dst);
    cudaEventRecord(evJoin, s2);

    // --- branch A (main): features + attn dots ---
    cudaMemsetAsync(p_wsum, 0, sizeof(float) * Pp);
    dim3 gFeat((Nn / 8 + 7) / 8, Pp);
    feat_kernel<<<gFeat, 256>>>(h, fc_w, attn_l, attn_r);

    // join: weight pass needs CSR (s2) and el/er (main)
    cudaStreamWaitEvent(0, evJoin, 0);

    weight_kernel<<<(unsigned)((PE + 255) / 256), 256>>>();
    agg_kernel<<<(TOT + 7) / 8, 256>>>();

    dim3 gSem((Nn + 63) / 64, Pp);
    sem_kernel<<<gSem, 256>>>(bias, sem_w1, sem_b1, sem_w2);

    final_kernel<<<((size_t)Nn * 32 + 255) / 256, 256>>>(bias, out);
}

// round 12
// speedup vs baseline: 1.3199x; 1.3199x over previous
#include <cuda_runtime.h>
#include <cuda_bf16.h>
#include <cuda_fp16.h>
#include <math.h>

#define Nn 50000
#define Ee 800000
#define Pp 2
#define Hh 4
#define Ff 32
#define HF 128
#define INF 128
#define TOT (Pp * Nn)          // 100000 destination slots
#define SCAN_B 98              // ceil(TOT/1024)
#define CHUNK 16               // agg staging chunk (edges)

// ---- scratch (device globals; allocation-free) ----
__device__ __half g_feat_h[(size_t)Pp * Nn * HF]; // 25.6 MB (gather path)
__device__ float g_el[(size_t)Pp * Nn * Hh];
__device__ float g_er[(size_t)Pp * Nn * Hh];
__device__ float g_out[(size_t)Pp * Nn * HF];    // 51.2 MB
__device__ float g_wsum[Pp];
__device__ int   g_deg[TOT];
__device__ int   g_off[TOT];
__device__ int   g_cur[TOT];
__device__ int   g_bsum[SCAN_B];
__device__ int   g_csr_src[(size_t)Pp * Ee + 32];     // src ids, CSR order

// ---- packed fp32x2 helpers (Blackwell) ----
__device__ __forceinline__ unsigned long long pack2(float a, float b) {
    unsigned long long r;
    asm("mov.b64 %0, {%1, %2};" : "=l"(r) : "f"(a), "f"(b));
    return r;
}
__device__ __forceinline__ void unpack2(unsigned long long v, float& a, float& b) {
    asm("mov.b64 {%0, %1}, %2;" : "=f"(a), "=f"(b) : "l"(v));
}
__device__ __forceinline__ unsigned long long fma2(unsigned long long a,
                                                   unsigned long long b,
                                                   unsigned long long c) {
    unsigned long long r;
    asm("fma.rn.f32x2 %0, %1, %2, %3;" : "=l"(r) : "l"(a), "l"(b), "l"(c));
    return r;
}
__device__ __forceinline__ void cp_async16(unsigned int smem_addr, const void* gptr) {
    asm volatile("cp.async.cg.shared.global [%0], [%1], 16;"
                 :: "r"(smem_addr), "l"(gptr) : "memory");
}
__device__ __forceinline__ void cp_async_commit_wait0() {
    asm volatile("cp.async.commit_group;\n\tcp.async.wait_group 0;" ::: "memory");
}

// ============================================================
// K1: feat = h @ W_p (stored fp16) ; el/er attn dots (fp32)
// warp = 8 nodes, lane = 4 consecutive cols
// ============================================================
__global__ void __launch_bounds__(256) feat_kernel(
                            const float* __restrict__ h,
                            const float* __restrict__ fc_w,
                            const float* __restrict__ attn_l,
                            const float* __restrict__ attn_r) {
    int p = blockIdx.y;
    const ulonglong2* W2 = (const ulonglong2*)(fc_w + (size_t)p * INF * HF);
    int warpId = threadIdx.x >> 5;
    int lane = threadIdx.x & 31;
    int gw = blockIdx.x * 8 + warpId;
    int n0 = gw * 8;                    // Nn % 8 == 0
    if (n0 >= Nn) return;

    const float4* h4 = (const float4*)h;

    unsigned long long acc[8][2];
    #pragma unroll
    for (int r = 0; r < 8; r++) { acc[r][0] = 0ull; acc[r][1] = 0ull; }

    for (int k4 = 0; k4 < 32; k4++) {
        float4 hv0 = __ldg(h4 + (size_t)(n0 + 0) * 32 + k4);
        float4 hv1 = __ldg(h4 + (size_t)(n0 + 1) * 32 + k4);
        float4 hv2 = __ldg(h4 + (size_t)(n0 + 2) * 32 + k4);
        float4 hv3 = __ldg(h4 + (size_t)(n0 + 3) * 32 + k4);
        float4 hv4 = __ldg(h4 + (size_t)(n0 + 4) * 32 + k4);
        float4 hv5 = __ldg(h4 + (size_t)(n0 + 5) * 32 + k4);
        float4 hv6 = __ldg(h4 + (size_t)(n0 + 6) * 32 + k4);
        float4 hv7 = __ldg(h4 + (size_t)(n0 + 7) * 32 + k4);
        float hs[8][4] = {
            {hv0.x, hv0.y, hv0.z, hv0.w}, {hv1.x, hv1.y, hv1.z, hv1.w},
            {hv2.x, hv2.y, hv2.z, hv2.w}, {hv3.x, hv3.y, hv3.z, hv3.w},
            {hv4.x, hv4.y, hv4.z, hv4.w}, {hv5.x, hv5.y, hv5.z, hv5.w},
            {hv6.x, hv6.y, hv6.z, hv6.w}, {hv7.x, hv7.y, hv7.z, hv7.w}};
        #pragma unroll
        for (int kk = 0; kk < 4; kk++) {
            ulonglong2 wv = W2[(size_t)(k4 * 4 + kk) * 32 + lane];
            #pragma unroll
            for (int r = 0; r < 8; r++) {
                unsigned long long pr = pack2(hs[r][kk], hs[r][kk]);
                acc[r][0] = fma2(pr, wv.x, acc[r][0]);
                acc[r][1] = fma2(pr, wv.y, acc[r][1]);
            }
        }
    }

    float4 accs[8];
    #pragma unroll
    for (int r = 0; r < 8; r++) {
        unpack2(acc[r][0], accs[r].x, accs[r].y);
        unpack2(acc[r][1], accs[r].z, accs[r].w);
    }

    uint2* feath = (uint2*)g_feat_h;
    #pragma unroll
    for (int r = 0; r < 8; r++) {
        __half2 a01 = __floats2half2_rn(accs[r].x, accs[r].y);
        __half2 a23 = __floats2half2_rn(accs[r].z, accs[r].w);
        uint2 st;
        st.x = *reinterpret_cast<unsigned int*>(&a01);
        st.y = *reinterpret_cast<unsigned int*>(&a23);
        feath[((size_t)p * Nn + n0 + r) * 32 + lane] = st;
    }

    float4 al4 = ((const float4*)(attn_l + (size_t)p * HF))[lane];
    float4 ar4 = ((const float4*)(attn_r + (size_t)p * HF))[lane];
    int head = lane >> 3;

    #pragma unroll
    for (int j = 0; j < 8; j++) {
        float pl = accs[j].x * al4.x + accs[j].y * al4.y + accs[j].z * al4.z + accs[j].w * al4.w;
        float pr = accs[j].x * ar4.x + accs[j].y * ar4.y + accs[j].z * ar4.z + accs[j].w * ar4.w;
        #pragma unroll
        for (int off = 4; off >= 1; off >>= 1) {
            pl += __shfl_xor_sync(0xffffffffu, pl, off);
            pr += __shfl_xor_sync(0xffffffffu, pr, off);
        }
        if ((lane & 7) == 0) {
            g_el[((size_t)p * Nn + n0 + j) * Hh + head] = pl;
            g_er[((size_t)p * Nn + n0 + j) * Hh + head] = pr;
        }
    }
}

// ============================================================
// CSR build: histogram -> scan -> scatter (src ids only)
// ============================================================
__global__ void hist_kernel(const int* __restrict__ dst) {
    int p = blockIdx.y;
    int e = blockIdx.x * 256 + threadIdx.x;
    if (e >= Ee) return;
    atomicAdd(&g_deg[p * Nn + __ldg(dst + (size_t)p * Ee + e)], 1);
}

__global__ void scan1_kernel() {
    __shared__ int wsum[32];
    int tid = threadIdx.x, lane = tid & 31, wid = tid >> 5;
    int i = blockIdx.x * 1024 + tid;
    int v = (i < TOT) ? g_deg[i] : 0;
    int x = v;
    #pragma unroll
    for (int o = 1; o < 32; o <<= 1) {
        int y = __shfl_up_sync(0xffffffffu, x, o);
        if (lane >= o) x += y;
    }
    if (lane == 31) wsum[wid] = x;
    __syncthreads();
    if (wid == 0) {
        int s = wsum[lane];
        #pragma unroll
        for (int o = 1; o < 32; o <<= 1) {
            int y = __shfl_up_sync(0xffffffffu, s, o);
            if (lane >= o) s += y;
        }
        wsum[lane] = s;
    }
    __syncthreads();
    int woff = (wid == 0) ? 0 : wsum[wid - 1];
    if (i < TOT) g_off[i] = woff + x - v;
    if (tid == 1023) g_bsum[blockIdx.x] = wsum[31];
}

__global__ void scan23_kernel() {
    __shared__ int sh_scan[SCAN_B];
    if (threadIdx.x < 32) {
        int lane = threadIdx.x;
        int v[4];
        int s = 0;
        #pragma unroll
        for (int j = 0; j < 4; j++) {
            int idx = lane * 4 + j;
            int t = (idx < SCAN_B) ? g_bsum[idx] : 0;
            v[j] = s;
            s += t;
        }
        int x = s;
        #pragma unroll
        for (int o = 1; o < 32; o <<= 1) {
            int y = __shfl_up_sync(0xffffffffu, x, o);
            if (lane >= o) x += y;
        }
        int excl = x - s;
        #pragma unroll
        for (int j = 0; j < 4; j++) {
            int idx = lane * 4 + j;
            if (idx < SCAN_B) sh_scan[idx] = excl + v[j];
        }
    }
    __syncthreads();
    int i = blockIdx.x * 1024 + threadIdx.x;
    if (i < TOT) {
        int o = g_off[i] + sh_scan[blockIdx.x];
        g_off[i] = o;
        g_cur[i] = o;
    }
}

__global__ void scatter_kernel(const int* __restrict__ src,
                               const int* __restrict__ dst) {
    int p = blockIdx.y;
    int e = blockIdx.x * 256 + threadIdx.x;
    if (e >= Ee) return;
    size_t idx = (size_t)p * Ee + e;
    int d = __ldg(dst + idx);
    int pos = atomicAdd(&g_cur[p * Nn + d], 1);
    g_csr_src[pos] = __ldg(src + idx);
}

// ============================================================
// K4: CSR aggregation — warp per dst node, cp.async staging.
// 16-edge chunks (4 KB staging per warp), 8 warps/block, 34 KB
// smem/block -> 6 blocks/SM = 48 warps/SM.
// ============================================================
__global__ void __launch_bounds__(256) agg_kernel() {
    __shared__ __align__(16) unsigned char s_feat[8][CHUNK * 256]; // 32 KB
    __shared__ float s_w[8][CHUNK * 4];                            // 2 KB

    int warpId = threadIdx.x >> 5;
    int lane = threadIdx.x & 31;
    int w = blockIdx.x * 8 + warpId;
    if (w >= TOT) return;
    int p = (w >= Nn) ? 1 : 0;
    size_t pbase = (size_t)p * Nn;

    int beg = g_off[w];
    int deg = g_deg[w];
    int head = lane >> 3;
    float erd = g_er[(size_t)w * Hh + head];

    const char* featg = (const char*)g_feat_h;
    unsigned int feat_s_base = (unsigned int)__cvta_generic_to_shared(&s_feat[warpId][0]);
    float* w_s = &s_w[warpId][0];

    unsigned long long a00 = 0ull, a01 = 0ull;
    unsigned long long a10 = 0ull, a11 = 0ull;
    float den = 0.f;

    for (int j = 0; j < deg; j += CHUNK) {
        int cnt = min(CHUNK, deg - j);
        // lane < CHUNK holds edge (j+lane)'s src id
        int s = g_csr_src[beg + j + min(lane, cnt - 1)];

        // phase 1: issue cp.async for all cnt feat rows (2 rows / step)
        int nsteps = (cnt + 1) >> 1;
        int sub = lane >> 4;          // 0 or 1: which of the 2 rows
        int boff = (lane & 15) * 16;  // byte offset within row
        #pragma unroll 8
        for (int r2 = 0; r2 < nsteps; r2++) {
            int row = r2 * 2 + sub;
            int sk = __shfl_sync(0xffffffffu, s, min(row, cnt - 1));
            if (row < cnt)
                cp_async16(feat_s_base + row * 256 + boff,
                           featg + ((pbase + sk) << 8) + boff);
        }

        // phase 2 (overlaps in-flight copies): weights for CHUNKx4
        // lane covers edge (q*8 + lane&7), head (lane>>3); layout [k][head]
        #pragma unroll
        for (int q = 0; q < CHUNK / 8; q++) {
            int ek = q * 8 + (lane & 7);
            int sk = __shfl_sync(0xffffffffu, s, min(ek, cnt - 1));
            float el = __ldg(g_el + (pbase + sk) * Hh + head);
            float v = el + erd; v = v > 0.f ? v : 0.2f * v;
            w_s[ek * 4 + head] = __expf(v);
        }

        cp_async_commit_wait0();
        __syncwarp();

        // phase 3: consume from smem
        const uint2* fs = (const uint2*)&s_feat[warpId][0];
        int k = 0;
        for (; k + 4 <= cnt; k += 4) {
            float w0 = w_s[(k + 0) * 4 + head];
            float w1 = w_s[(k + 1) * 4 + head];
            float w2 = w_s[(k + 2) * 4 + head];
            float w3 = w_s[(k + 3) * 4 + head];
            uint2 f0 = fs[(k + 0) * 32 + lane];
            uint2 f1 = fs[(k + 1) * 32 + lane];
            uint2 f2 = fs[(k + 2) * 32 + lane];
            uint2 f3 = fs[(k + 3) * 32 + lane];
            float2 f0a = __half22float2(*reinterpret_cast<__half2*>(&f0.x));
            float2 f0b = __half22float2(*reinterpret_cast<__half2*>(&f0.y));
            float2 f1a = __half22float2(*reinterpret_cast<__half2*>(&f1.x));
            float2 f1b = __half22float2(*reinterpret_cast<__half2*>(&f1.y));
            float2 f2a = __half22float2(*reinterpret_cast<__half2*>(&f2.x));
            float2 f2b = __half22float2(*reinterpret_cast<__half2*>(&f2.y));
            float2 f3a = __half22float2(*reinterpret_cast<__half2*>(&f3.x));
            float2 f3b = __half22float2(*reinterpret_cast<__half2*>(&f3.y));
            unsigned long long p0 = pack2(w0, w0);
            unsigned long long p1 = pack2(w1, w1);
            unsigned long long p2 = pack2(w2, w2);
            unsigned long long p3 = pack2(w3, w3);
            a00 = fma2(p0, pack2(f0a.x, f0a.y), a00);
            a01 = fma2(p0, pack2(f0b.x, f0b.y), a01);
            a10 = fma2(p1, pack2(f1a.x, f1a.y), a10);
            a11 = fma2(p1, pack2(f1b.x, f1b.y), a11);
            a00 = fma2(p2, pack2(f2a.x, f2a.y), a00);
            a01 = fma2(p2, pack2(f2b.x, f2b.y), a01);
            a10 = fma2(p3, pack2(f3a.x, f3a.y), a10);
            a11 = fma2(p3, pack2(f3b.x, f3b.y), a11);
            den += (w0 + w1) + (w2 + w3);
        }
        for (; k < cnt; k++) {
            float w0 = w_s[k * 4 + head];
            uint2 f0 = fs[k * 32 + lane];
            float2 f0a = __half22float2(*reinterpret_cast<__half2*>(&f0.x));
            float2 f0b = __half22float2(*reinterpret_cast<__half2*>(&f0.y));
            unsigned long long p0 = pack2(w0, w0);
            a00 = fma2(p0, pack2(f0a.x, f0a.y), a00);
            a01 = fma2(p0, pack2(f0b.x, f0b.y), a01);
            den += w0;
        }
        __syncwarp();   // all lanes done reading before next chunk overwrites
    }

    float ax0, ay0, az0, aw0, ax1, ay1, az1, aw1;
    unpack2(a00, ax0, ay0); unpack2(a01, az0, aw0);
    unpack2(a10, ax1, ay1); unpack2(a11, az1, aw1);
    float inv = 1.0f / fmaxf(den, 1e-9f);
    float4 r;
    r.x = (ax0 + ax1) * inv;
    r.y = (ay0 + ay1) * inv;
    r.z = (az0 + az1) * inv;
    r.w = (aw0 + aw1) * inv;
    ((float4*)g_out)[(size_t)w * 32 + lane] = r;
}

// ============================================================
// K5: semantic attention scores — 8 nodes/warp (halved W1 traffic)
// ============================================================
__global__ void __launch_bounds__(256) sem_kernel(
                           const float* __restrict__ bias,
                           const float* __restrict__ sem_w1,
                           const float* __restrict__ sem_b1,
                           const float* __restrict__ sem_w2) {
    __shared__ __align__(16) float z_sh[64 * HF];   // 32 KB
    int p = blockIdx.y;
    int base = blockIdx.x * 64;

    for (int i = threadIdx.x; i < 64 * HF; i += 256) {
        int node = base + (i >> 7);
        int c = i & 127;
        float z = 0.f;
        if (node < Nn) {
            float raw = g_out[((size_t)p * Nn + node) * HF + c] + bias[(size_t)p * HF + c];
            z = raw > 0.f ? raw : (__expf(raw) - 1.0f);
        }
        z_sh[i] = z;
    }
    __syncthreads();

    int warpId = threadIdx.x >> 5;
    int lane = threadIdx.x & 31;
    const ulonglong2* W2 = (const ulonglong2*)sem_w1;
    const float4* z4 = (const float4*)z_sh;

    unsigned long long acc[8][2];
    #pragma unroll
    for (int r = 0; r < 8; r++) { acc[r][0] = 0ull; acc[r][1] = 0ull; }

    for (int k4 = 0; k4 < 32; k4++) {
        float zs[8][4];
        #pragma unroll
        for (int r = 0; r < 8; r++) {
            float4 zv = z4[(warpId * 8 + r) * 32 + k4];
            zs[r][0] = zv.x; zs[r][1] = zv.y; zs[r][2] = zv.z; zs[r][3] = zv.w;
        }
        #pragma unroll
        for (int kk = 0; kk < 4; kk++) {
            ulonglong2 wv = W2[(size_t)(k4 * 4 + kk) * 32 + lane];
            #pragma unroll
            for (int r = 0; r < 8; r++) {
                unsigned long long pr = pack2(zs[r][kk], zs[r][kk]);
                acc[r][0] = fma2(pr, wv.x, acc[r][0]);
                acc[r][1] = fma2(pr, wv.y, acc[r][1]);
            }
        }
    }

    float4 b14 = ((const float4*)sem_b1)[lane];
    float4 w24 = ((const float4*)sem_w2)[lane];

    float total = 0.f;
    #pragma unroll
    for (int j = 0; j < 8; j++) {
        float4 a;
        unpack2(acc[j][0], a.x, a.y);
        unpack2(acc[j][1], a.z, a.w);
        float cj = tanhf(a.x + b14.x) * w24.x
                 + tanhf(a.y + b14.y) * w24.y
                 + tanhf(a.z + b14.z) * w24.z
                 + tanhf(a.w + b14.w) * w24.w;
        #pragma unroll
        for (int off = 16; off >= 1; off >>= 1)
            cj += __shfl_xor_sync(0xffffffffu, cj, off);
        int node = base + warpId * 8 + j;
        if (node < Nn) total += cj;
    }
    if (lane == 0) atomicAdd(&g_wsum[p], total);
}

// ============================================================
// K6: combine with semantic softmax
// ============================================================
__global__ void final_kernel(const float* __restrict__ bias,
                             float* __restrict__ out) {
    size_t i = (size_t)blockIdx.x * 256 + threadIdx.x;
    if (i >= (size_t)Nn * 32) return;
    float w0 = g_wsum[0] * (1.0f / Nn);
    float w1 = g_wsum[1] * (1.0f / Nn);
    float m = fmaxf(w0, w1);
    float e0 = __expf(w0 - m), e1 = __expf(w1 - m);
    float inv = 1.0f / (e0 + e1);
    float b0 = e0 * inv, b1 = e1 * inv;

    int c4 = (int)(i & 31);
    float4 r0 = ((const float4*)g_out)[i];
    float4 r1 = ((const float4*)g_out)[(size_t)Nn * 32 + i];
    float4 bi0 = ((const float4*)bias)[c4];
    float4 bi1 = ((const float4*)bias)[32 + c4];

    float4 res;
    float v;
    v = r0.x + bi0.x; v = v > 0.f ? v : (__expf(v) - 1.f); res.x = b0 * v;
    v = r0.y + bi0.y; v = v > 0.f ? v : (__expf(v) - 1.f); res.y = b0 * v;
    v = r0.z + bi0.z; v = v > 0.f ? v : (__expf(v) - 1.f); res.z = b0 * v;
    v = r0.w + bi0.w; v = v > 0.f ? v : (__expf(v) - 1.f); res.w = b0 * v;
    v = r1.x + bi1.x; v = v > 0.f ? v : (__expf(v) - 1.f); res.x += b1 * v;
    v = r1.y + bi1.y; v = v > 0.f ? v : (__expf(v) - 1.f); res.y += b1 * v;
    v = r1.z + bi1.z; v = v > 0.f ? v : (__expf(v) - 1.f); res.z += b1 * v;
    v = r1.w + bi1.w; v = v > 0.f ? v : (__expf(v) - 1.f); res.w += b1 * v;

    ((float4*)out)[i] = res;
}

extern "C" void kernel_launch(void* const* d_in, const int* in_sizes, int n_in,
                              void* d_out, int out_size) {
    const float* h      = (const float*)d_in[0];
    const int*   src    = (const int*)  d_in[1];
    const int*   dst    = (const int*)  d_in[2];
    const float* fc_w   = (const float*)d_in[3];
    const float* attn_l = (const float*)d_in[4];
    const float* attn_r = (const float*)d_in[5];
    const float* bias   = (const float*)d_in[6];
    const float* sem_w1 = (const float*)d_in[7];
    const float* sem_b1 = (const float*)d_in[8];
    const float* sem_w2 = (const float*)d_in[9];
    float* out = (float*)d_out;

    static cudaStream_t s2 = nullptr;
    static cudaEvent_t evFork = nullptr, evJoin = nullptr;
    if (s2 == nullptr) {
        cudaStreamCreateWithFlags(&s2, cudaStreamNonBlocking);
        cudaEventCreateWithFlags(&evFork, cudaEventDisableTiming);
        cudaEventCreateWithFlags(&evJoin, cudaEventDisableTiming);
    }

    void *p_deg, *p_wsum;
    cudaGetSymbolAddress(&p_deg, g_deg);
    cudaGetSymbolAddress(&p_wsum, g_wsum);

    // fork: full CSR build (hist+scan+scatter) on s2, feat GEMM on main
    cudaEventRecord(evFork, 0);
    cudaStreamWaitEvent(s2, evFork, 0);

    // --- branch B (s2): histogram + offsets + scatter ---
    cudaMemsetAsync(p_deg, 0, sizeof(int) * TOT, s2);
    dim3 gEdge((Ee + 255) / 256, Pp);
    hist_kernel<<<gEdge, 256, 0, s2>>>(dst);
    scan1_kernel<<<SCAN_B, 1024, 0, s2>>>();
    scan23_kernel<<<SCAN_B, 1024, 0, s2>>>();
    scatter_kernel<<<gEdge, 256, 0, s2>>>(src, dst);
    cudaEventRecord(evJoin, s2);

    // --- branch A (main): features + attn dots ---
    cudaMemsetAsync(p_wsum, 0, sizeof(float) * Pp);
    dim3 gFeat((Nn / 8 + 7) / 8, Pp);
    feat_kernel<<<gFeat, 256>>>(h, fc_w, attn_l, attn_r);

    // join: agg needs CSR (s2) and feat/el/er (main)
    cudaStreamWaitEvent(0, evJoin, 0);

    agg_kernel<<<(TOT + 7) / 8, 256>>>();

    dim3 gSem((Nn + 63) / 64, Pp);
    sem_kernel<<<gSem, 256>>>(bias, sem_w1, sem_b1, sem_w2);

    final_kernel<<<((size_t)Nn * 32 + 255) / 256, 256>>>(bias, out);
}

// round 13
// speedup vs baseline: 1.3469x; 1.0204x over previous
#include <cuda_runtime.h>
#include <cuda_bf16.h>
#include <cuda_fp16.h>
#include <math.h>

#define Nn 50000
#define Ee 800000
#define Pp 2
#define Hh 4
#define Ff 32
#define HF 128
#define INF 128
#define TOT (Pp * Nn)          // 100000 destination slots
#define SCAN_B 98              // ceil(TOT/1024)
#define CHUNK 16               // agg staging chunk (edges)

// ---- scratch (device globals; allocation-free) ----
__device__ __half g_feat_h[(size_t)Pp * Nn * HF]; // 25.6 MB (gather path)
__device__ float g_el[(size_t)Pp * Nn * Hh];
__device__ float g_er[(size_t)Pp * Nn * Hh];
__device__ float g_out[(size_t)Pp * Nn * HF];    // 51.2 MB
__device__ float g_wsum[Pp];
__device__ int   g_deg[TOT];
__device__ int   g_off[TOT];
__device__ int   g_cur[TOT];
__device__ int   g_bsum[SCAN_B];
__device__ int   g_csr_src[(size_t)Pp * Ee + 32];     // src ids, CSR order

// ---- packed fp32x2 helpers (Blackwell) ----
__device__ __forceinline__ unsigned long long pack2(float a, float b) {
    unsigned long long r;
    asm("mov.b64 %0, {%1, %2};" : "=l"(r) : "f"(a), "f"(b));
    return r;
}
__device__ __forceinline__ void unpack2(unsigned long long v, float& a, float& b) {
    asm("mov.b64 {%0, %1}, %2;" : "=f"(a), "=f"(b) : "l"(v));
}
__device__ __forceinline__ unsigned long long fma2(unsigned long long a,
                                                   unsigned long long b,
                                                   unsigned long long c) {
    unsigned long long r;
    asm("fma.rn.f32x2 %0, %1, %2, %3;" : "=l"(r) : "l"(a), "l"(b), "l"(c));
    return r;
}
__device__ __forceinline__ void cp_async16(unsigned int smem_addr, const void* gptr) {
    asm volatile("cp.async.cg.shared.global [%0], [%1], 16;"
                 :: "r"(smem_addr), "l"(gptr) : "memory");
}
__device__ __forceinline__ void cp_async_commit_wait0() {
    asm volatile("cp.async.commit_group;\n\tcp.async.wait_group 0;" ::: "memory");
}

// ============================================================
// K1: feat = h @ W_p (stored fp16) ; el/er attn dots (fp32)
// warp = 8 nodes, lane = 4 consecutive cols
// ============================================================
__global__ void __launch_bounds__(256) feat_kernel(
                            const float* __restrict__ h,
                            const float* __restrict__ fc_w,
                            const float* __restrict__ attn_l,
                            const float* __restrict__ attn_r) {
    int p = blockIdx.y;
    const ulonglong2* W2 = (const ulonglong2*)(fc_w + (size_t)p * INF * HF);
    int warpId = threadIdx.x >> 5;
    int lane = threadIdx.x & 31;
    int gw = blockIdx.x * 8 + warpId;
    int n0 = gw * 8;                    // Nn % 8 == 0
    if (n0 >= Nn) return;

    const float4* h4 = (const float4*)h;

    unsigned long long acc[8][2];
    #pragma unroll
    for (int r = 0; r < 8; r++) { acc[r][0] = 0ull; acc[r][1] = 0ull; }

    for (int k4 = 0; k4 < 32; k4++) {
        float4 hv0 = __ldg(h4 + (size_t)(n0 + 0) * 32 + k4);
        float4 hv1 = __ldg(h4 + (size_t)(n0 + 1) * 32 + k4);
        float4 hv2 = __ldg(h4 + (size_t)(n0 + 2) * 32 + k4);
        float4 hv3 = __ldg(h4 + (size_t)(n0 + 3) * 32 + k4);
        float4 hv4 = __ldg(h4 + (size_t)(n0 + 4) * 32 + k4);
        float4 hv5 = __ldg(h4 + (size_t)(n0 + 5) * 32 + k4);
        float4 hv6 = __ldg(h4 + (size_t)(n0 + 6) * 32 + k4);
        float4 hv7 = __ldg(h4 + (size_t)(n0 + 7) * 32 + k4);
        float hs[8][4] = {
            {hv0.x, hv0.y, hv0.z, hv0.w}, {hv1.x, hv1.y, hv1.z, hv1.w},
            {hv2.x, hv2.y, hv2.z, hv2.w}, {hv3.x, hv3.y, hv3.z, hv3.w},
            {hv4.x, hv4.y, hv4.z, hv4.w}, {hv5.x, hv5.y, hv5.z, hv5.w},
            {hv6.x, hv6.y, hv6.z, hv6.w}, {hv7.x, hv7.y, hv7.z, hv7.w}};
        #pragma unroll
        for (int kk = 0; kk < 4; kk++) {
            ulonglong2 wv = W2[(size_t)(k4 * 4 + kk) * 32 + lane];
            #pragma unroll
            for (int r = 0; r < 8; r++) {
                unsigned long long pr = pack2(hs[r][kk], hs[r][kk]);
                acc[r][0] = fma2(pr, wv.x, acc[r][0]);
                acc[r][1] = fma2(pr, wv.y, acc[r][1]);
            }
        }
    }

    float4 accs[8];
    #pragma unroll
    for (int r = 0; r < 8; r++) {
        unpack2(acc[r][0], accs[r].x, accs[r].y);
        unpack2(acc[r][1], accs[r].z, accs[r].w);
    }

    uint2* feath = (uint2*)g_feat_h;
    #pragma unroll
    for (int r = 0; r < 8; r++) {
        __half2 a01 = __floats2half2_rn(accs[r].x, accs[r].y);
        __half2 a23 = __floats2half2_rn(accs[r].z, accs[r].w);
        uint2 st;
        st.x = *reinterpret_cast<unsigned int*>(&a01);
        st.y = *reinterpret_cast<unsigned int*>(&a23);
        feath[((size_t)p * Nn + n0 + r) * 32 + lane] = st;
    }

    float4 al4 = ((const float4*)(attn_l + (size_t)p * HF))[lane];
    float4 ar4 = ((const float4*)(attn_r + (size_t)p * HF))[lane];
    int head = lane >> 3;

    #pragma unroll
    for (int j = 0; j < 8; j++) {
        float pl = accs[j].x * al4.x + accs[j].y * al4.y + accs[j].z * al4.z + accs[j].w * al4.w;
        float pr = accs[j].x * ar4.x + accs[j].y * ar4.y + accs[j].z * ar4.z + accs[j].w * ar4.w;
        #pragma unroll
        for (int off = 4; off >= 1; off >>= 1) {
            pl += __shfl_xor_sync(0xffffffffu, pl, off);
            pr += __shfl_xor_sync(0xffffffffu, pr, off);
        }
        if ((lane & 7) == 0) {
            g_el[((size_t)p * Nn + n0 + j) * Hh + head] = pl;
            g_er[((size_t)p * Nn + n0 + j) * Hh + head] = pr;
        }
    }
}

// ============================================================
// CSR build: histogram -> scan -> scatter (src ids only)
// ============================================================
__global__ void hist_kernel(const int* __restrict__ dst) {
    int p = blockIdx.y;
    int e = blockIdx.x * 256 + threadIdx.x;
    if (e >= Ee) return;
    atomicAdd(&g_deg[p * Nn + __ldg(dst + (size_t)p * Ee + e)], 1);
}

__global__ void scan1_kernel() {
    __shared__ int wsum[32];
    int tid = threadIdx.x, lane = tid & 31, wid = tid >> 5;
    int i = blockIdx.x * 1024 + tid;
    int v = (i < TOT) ? g_deg[i] : 0;
    int x = v;
    #pragma unroll
    for (int o = 1; o < 32; o <<= 1) {
        int y = __shfl_up_sync(0xffffffffu, x, o);
        if (lane >= o) x += y;
    }
    if (lane == 31) wsum[wid] = x;
    __syncthreads();
    if (wid == 0) {
        int s = wsum[lane];
        #pragma unroll
        for (int o = 1; o < 32; o <<= 1) {
            int y = __shfl_up_sync(0xffffffffu, s, o);
            if (lane >= o) s += y;
        }
        wsum[lane] = s;
    }
    __syncthreads();
    int woff = (wid == 0) ? 0 : wsum[wid - 1];
    if (i < TOT) g_off[i] = woff + x - v;
    if (tid == 1023) g_bsum[blockIdx.x] = wsum[31];
}

__global__ void scan23_kernel() {
    __shared__ int sh_scan[SCAN_B];
    if (threadIdx.x < 32) {
        int lane = threadIdx.x;
        int v[4];
        int s = 0;
        #pragma unroll
        for (int j = 0; j < 4; j++) {
            int idx = lane * 4 + j;
            int t = (idx < SCAN_B) ? g_bsum[idx] : 0;
            v[j] = s;
            s += t;
        }
        int x = s;
        #pragma unroll
        for (int o = 1; o < 32; o <<= 1) {
            int y = __shfl_up_sync(0xffffffffu, x, o);
            if (lane >= o) x += y;
        }
        int excl = x - s;
        #pragma unroll
        for (int j = 0; j < 4; j++) {
            int idx = lane * 4 + j;
            if (idx < SCAN_B) sh_scan[idx] = excl + v[j];
        }
    }
    __syncthreads();
    int i = blockIdx.x * 1024 + threadIdx.x;
    if (i < TOT) {
        int o = g_off[i] + sh_scan[blockIdx.x];
        g_off[i] = o;
        g_cur[i] = o;
    }
}

__global__ void scatter_kernel(const int* __restrict__ src,
                               const int* __restrict__ dst) {
    int p = blockIdx.y;
    int e = blockIdx.x * 256 + threadIdx.x;
    if (e >= Ee) return;
    size_t idx = (size_t)p * Ee + e;
    int d = __ldg(dst + idx);
    int pos = atomicAdd(&g_cur[p * Nn + d], 1);
    g_csr_src[pos] = __ldg(src + idx);
}

// ============================================================
// K4: CSR aggregation — warp per dst node, cp.async staging.
// 16-edge chunks, 8 warps/block, 34 KB smem. Per-metapath launch
// (p passed in) so sem(p) can pipeline against agg(p+1).
// ============================================================
__global__ void __launch_bounds__(256) agg_kernel(int p) {
    __shared__ __align__(16) unsigned char s_feat[8][CHUNK * 256]; // 32 KB
    __shared__ float s_w[8][CHUNK * 4];                            // 2 KB

    int warpId = threadIdx.x >> 5;
    int lane = threadIdx.x & 31;
    int wl = blockIdx.x * 8 + warpId;
    if (wl >= Nn) return;
    int w = p * Nn + wl;
    size_t pbase = (size_t)p * Nn;

    int beg = g_off[w];
    int deg = g_deg[w];
    int head = lane >> 3;
    float erd = g_er[(size_t)w * Hh + head];

    const char* featg = (const char*)g_feat_h;
    unsigned int feat_s_base = (unsigned int)__cvta_generic_to_shared(&s_feat[warpId][0]);
    float* w_s = &s_w[warpId][0];

    unsigned long long a00 = 0ull, a01 = 0ull;
    unsigned long long a10 = 0ull, a11 = 0ull;
    float den = 0.f;

    for (int j = 0; j < deg; j += CHUNK) {
        int cnt = min(CHUNK, deg - j);
        // lane < CHUNK holds edge (j+lane)'s src id
        int s = g_csr_src[beg + j + min(lane, cnt - 1)];

        // phase 1: issue cp.async for all cnt feat rows (2 rows / step)
        int nsteps = (cnt + 1) >> 1;
        int sub = lane >> 4;          // 0 or 1: which of the 2 rows
        int boff = (lane & 15) * 16;  // byte offset within row
        #pragma unroll 8
        for (int r2 = 0; r2 < nsteps; r2++) {
            int row = r2 * 2 + sub;
            int sk = __shfl_sync(0xffffffffu, s, min(row, cnt - 1));
            if (row < cnt)
                cp_async16(feat_s_base + row * 256 + boff,
                           featg + ((pbase + sk) << 8) + boff);
        }

        // phase 2 (overlaps in-flight copies): weights for CHUNKx4
        #pragma unroll
        for (int q = 0; q < CHUNK / 8; q++) {
            int ek = q * 8 + (lane & 7);
            int sk = __shfl_sync(0xffffffffu, s, min(ek, cnt - 1));
            float el = __ldg(g_el + (pbase + sk) * Hh + head);
            float v = el + erd; v = v > 0.f ? v : 0.2f * v;
            w_s[ek * 4 + head] = __expf(v);
        }

        cp_async_commit_wait0();
        __syncwarp();

        // phase 3: consume from smem
        const uint2* fs = (const uint2*)&s_feat[warpId][0];
        int k = 0;
        for (; k + 4 <= cnt; k += 4) {
            float w0 = w_s[(k + 0) * 4 + head];
            float w1 = w_s[(k + 1) * 4 + head];
            float w2 = w_s[(k + 2) * 4 + head];
            float w3 = w_s[(k + 3) * 4 + head];
            uint2 f0 = fs[(k + 0) * 32 + lane];
            uint2 f1 = fs[(k + 1) * 32 + lane];
            uint2 f2 = fs[(k + 2) * 32 + lane];
            uint2 f3 = fs[(k + 3) * 32 + lane];
            float2 f0a = __half22float2(*reinterpret_cast<__half2*>(&f0.x));
            float2 f0b = __half22float2(*reinterpret_cast<__half2*>(&f0.y));
            float2 f1a = __half22float2(*reinterpret_cast<__half2*>(&f1.x));
            float2 f1b = __half22float2(*reinterpret_cast<__half2*>(&f1.y));
            float2 f2a = __half22float2(*reinterpret_cast<__half2*>(&f2.x));
            float2 f2b = __half22float2(*reinterpret_cast<__half2*>(&f2.y));
            float2 f3a = __half22float2(*reinterpret_cast<__half2*>(&f3.x));
            float2 f3b = __half22float2(*reinterpret_cast<__half2*>(&f3.y));
            unsigned long long p0 = pack2(w0, w0);
            unsigned long long p1 = pack2(w1, w1);
            unsigned long long p2 = pack2(w2, w2);
            unsigned long long p3 = pack2(w3, w3);
            a00 = fma2(p0, pack2(f0a.x, f0a.y), a00);
            a01 = fma2(p0, pack2(f0b.x, f0b.y), a01);
            a10 = fma2(p1, pack2(f1a.x, f1a.y), a10);
            a11 = fma2(p1, pack2(f1b.x, f1b.y), a11);
            a00 = fma2(p2, pack2(f2a.x, f2a.y), a00);
            a01 = fma2(p2, pack2(f2b.x, f2b.y), a01);
            a10 = fma2(p3, pack2(f3a.x, f3a.y), a10);
            a11 = fma2(p3, pack2(f3b.x, f3b.y), a11);
            den += (w0 + w1) + (w2 + w3);
        }
        for (; k < cnt; k++) {
            float w0 = w_s[k * 4 + head];
            uint2 f0 = fs[k * 32 + lane];
            float2 f0a = __half22float2(*reinterpret_cast<__half2*>(&f0.x));
            float2 f0b = __half22float2(*reinterpret_cast<__half2*>(&f0.y));
            unsigned long long p0 = pack2(w0, w0);
            a00 = fma2(p0, pack2(f0a.x, f0a.y), a00);
            a01 = fma2(p0, pack2(f0b.x, f0b.y), a01);
            den += w0;
        }
        __syncwarp();   // all lanes done reading before next chunk overwrites
    }

    float ax0, ay0, az0, aw0, ax1, ay1, az1, aw1;
    unpack2(a00, ax0, ay0); unpack2(a01, az0, aw0);
    unpack2(a10, ax1, ay1); unpack2(a11, az1, aw1);
    float inv = 1.0f / fmaxf(den, 1e-9f);
    float4 r;
    r.x = (ax0 + ax1) * inv;
    r.y = (ay0 + ay1) * inv;
    r.z = (az0 + az1) * inv;
    r.w = (aw0 + aw1) * inv;
    ((float4*)g_out)[(size_t)w * 32 + lane] = r;
}

// ============================================================
// K5: semantic attention scores — round-10 4-row form,
// per-metapath launch (p passed in).
// ============================================================
__global__ void sem_kernel(int p,
                           const float* __restrict__ bias,
                           const float* __restrict__ sem_w1,
                           const float* __restrict__ sem_b1,
                           const float* __restrict__ sem_w2) {
    __shared__ __align__(16) float z_sh[32 * HF];
    int base = blockIdx.x * 32;

    for (int i = threadIdx.x; i < 32 * HF; i += 256) {
        int node = base + (i >> 7);
        int c = i & 127;
        float z = 0.f;
        if (node < Nn) {
            float raw = g_out[((size_t)p * Nn + node) * HF + c] + bias[(size_t)p * HF + c];
            z = raw > 0.f ? raw : (__expf(raw) - 1.0f);
        }
        z_sh[i] = z;
    }
    __syncthreads();

    int warpId = threadIdx.x >> 5;
    int lane = threadIdx.x & 31;
    const ulonglong2* W2 = (const ulonglong2*)sem_w1;
    const float4* z4 = (const float4*)z_sh;

    unsigned long long acc[4][2];
    #pragma unroll
    for (int r = 0; r < 4; r++) { acc[r][0] = 0ull; acc[r][1] = 0ull; }

    for (int k4 = 0; k4 < 32; k4++) {
        float4 zv0 = z4[(warpId * 4 + 0) * 32 + k4];
        float4 zv1 = z4[(warpId * 4 + 1) * 32 + k4];
        float4 zv2 = z4[(warpId * 4 + 2) * 32 + k4];
        float4 zv3 = z4[(warpId * 4 + 3) * 32 + k4];
        float z0v[4] = {zv0.x, zv0.y, zv0.z, zv0.w};
        float z1v[4] = {zv1.x, zv1.y, zv1.z, zv1.w};
        float z2v[4] = {zv2.x, zv2.y, zv2.z, zv2.w};
        float z3v[4] = {zv3.x, zv3.y, zv3.z, zv3.w};
        #pragma unroll
        for (int kk = 0; kk < 4; kk++) {
            ulonglong2 wv = W2[(size_t)(k4 * 4 + kk) * 32 + lane];
            unsigned long long p0 = pack2(z0v[kk], z0v[kk]);
            unsigned long long p1 = pack2(z1v[kk], z1v[kk]);
            unsigned long long p2 = pack2(z2v[kk], z2v[kk]);
            unsigned long long p3 = pack2(z3v[kk], z3v[kk]);
            acc[0][0] = fma2(p0, wv.x, acc[0][0]); acc[0][1] = fma2(p0, wv.y, acc[0][1]);
            acc[1][0] = fma2(p1, wv.x, acc[1][0]); acc[1][1] = fma2(p1, wv.y, acc[1][1]);
            acc[2][0] = fma2(p2, wv.x, acc[2][0]); acc[2][1] = fma2(p2, wv.y, acc[2][1]);
            acc[3][0] = fma2(p3, wv.x, acc[3][0]); acc[3][1] = fma2(p3, wv.y, acc[3][1]);
        }
    }

    float4 b14 = ((const float4*)sem_b1)[lane];
    float4 w24 = ((const float4*)sem_w2)[lane];

    float total = 0.f;
    #pragma unroll
    for (int j = 0; j < 4; j++) {
        float4 a;
        unpack2(acc[j][0], a.x, a.y);
        unpack2(acc[j][1], a.z, a.w);
        float cj = tanhf(a.x + b14.x) * w24.x
                 + tanhf(a.y + b14.y) * w24.y
                 + tanhf(a.z + b14.z) * w24.z
                 + tanhf(a.w + b14.w) * w24.w;
        #pragma unroll
        for (int off = 16; off >= 1; off >>= 1)
            cj += __shfl_xor_sync(0xffffffffu, cj, off);
        int node = base + warpId * 4 + j;
        if (node < Nn) total += cj;
    }
    if (lane == 0) atomicAdd(&g_wsum[p], total);
}

// ============================================================
// K6: combine with semantic softmax
// ============================================================
__global__ void final_kernel(const float* __restrict__ bias,
                             float* __restrict__ out) {
    size_t i = (size_t)blockIdx.x * 256 + threadIdx.x;
    if (i >= (size_t)Nn * 32) return;
    float w0 = g_wsum[0] * (1.0f / Nn);
    float w1 = g_wsum[1] * (1.0f / Nn);
    float m = fmaxf(w0, w1);
    float e0 = __expf(w0 - m), e1 = __expf(w1 - m);
    float inv = 1.0f / (e0 + e1);
    float b0 = e0 * inv, b1 = e1 * inv;

    int c4 = (int)(i & 31);
    float4 r0 = ((const float4*)g_out)[i];
    float4 r1 = ((const float4*)g_out)[(size_t)Nn * 32 + i];
    float4 bi0 = ((const float4*)bias)[c4];
    float4 bi1 = ((const float4*)bias)[32 + c4];

    float4 res;
    float v;
    v = r0.x + bi0.x; v = v > 0.f ? v : (__expf(v) - 1.f); res.x = b0 * v;
    v = r0.y + bi0.y; v = v > 0.f ? v : (__expf(v) - 1.f); res.y = b0 * v;
    v = r0.z + bi0.z; v = v > 0.f ? v : (__expf(v) - 1.f); res.z = b0 * v;
    v = r0.w + bi0.w; v = v > 0.f ? v : (__expf(v) - 1.f); res.w = b0 * v;
    v = r1.x + bi1.x; v = v > 0.f ? v : (__expf(v) - 1.f); res.x += b1 * v;
    v = r1.y + bi1.y; v = v > 0.f ? v : (__expf(v) - 1.f); res.y += b1 * v;
    v = r1.z + bi1.z; v = v > 0.f ? v : (__expf(v) - 1.f); res.z += b1 * v;
    v = r1.w + bi1.w; v = v > 0.f ? v : (__expf(v) - 1.f); res.w += b1 * v;

    ((float4*)out)[i] = res;
}

extern "C" void kernel_launch(void* const* d_in, const int* in_sizes, int n_in,
                              void* d_out, int out_size) {
    const float* h      = (const float*)d_in[0];
    const int*   src    = (const int*)  d_in[1];
    const int*   dst    = (const int*)  d_in[2];
    const float* fc_w   = (const float*)d_in[3];
    const float* attn_l = (const float*)d_in[4];
    const float* attn_r = (const float*)d_in[5];
    const float* bias   = (const float*)d_in[6];
    const float* sem_w1 = (const float*)d_in[7];
    const float* sem_b1 = (const float*)d_in[8];
    const float* sem_w2 = (const float*)d_in[9];
    float* out = (float*)d_out;

    static cudaStream_t s2 = nullptr;
    static cudaEvent_t evFork = nullptr, evJoin = nullptr, evA0 = nullptr, evS0 = nullptr;
    if (s2 == nullptr) {
        cudaStreamCreateWithFlags(&s2, cudaStreamNonBlocking);
        cudaEventCreateWithFlags(&evFork, cudaEventDisableTiming);
        cudaEventCreateWithFlags(&evJoin, cudaEventDisableTiming);
        cudaEventCreateWithFlags(&evA0, cudaEventDisableTiming);
        cudaEventCreateWithFlags(&evS0, cudaEventDisableTiming);
    }

    void *p_deg, *p_wsum;
    cudaGetSymbolAddress(&p_deg, g_deg);
    cudaGetSymbolAddress(&p_wsum, g_wsum);

    // fork: full CSR build (hist+scan+scatter) on s2, feat GEMM on main
    cudaEventRecord(evFork, 0);
    cudaStreamWaitEvent(s2, evFork, 0);

    // --- branch B (s2): histogram + offsets + scatter ---
    cudaMemsetAsync(p_deg, 0, sizeof(int) * TOT, s2);
    dim3 gEdge((Ee + 255) / 256, Pp);
    hist_kernel<<<gEdge, 256, 0, s2>>>(dst);
    scan1_kernel<<<SCAN_B, 1024, 0, s2>>>();
    scan23_kernel<<<SCAN_B, 1024, 0, s2>>>();
    scatter_kernel<<<gEdge, 256, 0, s2>>>(src, dst);
    cudaEventRecord(evJoin, s2);

    // --- branch A (main): features + attn dots ---
    cudaMemsetAsync(p_wsum, 0, sizeof(float) * Pp);
    dim3 gFeat((Nn / 8 + 7) / 8, Pp);
    feat_kernel<<<gFeat, 256>>>(h, fc_w, attn_l, attn_r);

    // join: agg needs CSR (s2) and feat/el/er (main)
    cudaStreamWaitEvent(0, evJoin, 0);

    // pipelined per-metapath: sem(p=0) on s2 overlaps agg(p=1) on main
    agg_kernel<<<(Nn + 7) / 8, 256>>>(0);
    cudaEventRecord(evA0, 0);
    cudaStreamWaitEvent(s2, evA0, 0);
    sem_kernel<<<(Nn + 31) / 32, 256, 0, s2>>>(0, bias, sem_w1, sem_b1, sem_w2);
    cudaEventRecord(evS0, s2);

    agg_kernel<<<(Nn + 7) / 8, 256>>>(1);
    sem_kernel<<<(Nn + 31) / 32, 256>>>(1, bias, sem_w1, sem_b1, sem_w2);

    cudaStreamWaitEvent(0, evS0, 0);
    final_kernel<<<((size_t)Nn * 32 + 255) / 256, 256>>>(bias, out);
}

// round 16
// speedup vs baseline: 1.3919x; 1.0334x over previous
#include <cuda_runtime.h>
#include <cuda_bf16.h>
#include <cuda_fp16.h>
#include <math.h>

#define Nn 50000
#define Ee 800000
#define Pp 2
#define Hh 4
#define Ff 32
#define HF 128
#define INF 128
#define TOT (Pp * Nn)          // 100000 destination slots
#define SCAN_B 98              // ceil(TOT/1024)
#define CHUNK 16               // agg staging chunk (edges)

// ---- scratch (device globals; allocation-free) ----
__device__ __half g_feat_h[(size_t)Pp * Nn * HF]; // 25.6 MB (gather path)
__device__ float g_el[(size_t)Pp * Nn * Hh];
__device__ float g_er[(size_t)Pp * Nn * Hh];
__device__ float g_out[(size_t)Pp * Nn * HF];    // 51.2 MB
__device__ float g_wsum[Pp];
__device__ int   g_deg[TOT];
__device__ int   g_off[TOT];
__device__ int   g_cur[TOT];
__device__ int   g_bsum[SCAN_B];
__device__ int   g_csr_src[(size_t)Pp * Ee + 32];     // src ids, CSR order

// ---- packed fp32x2 helpers (Blackwell) ----
__device__ __forceinline__ unsigned long long pack2(float a, float b) {
    unsigned long long r;
    asm("mov.b64 %0, {%1, %2};" : "=l"(r) : "f"(a), "f"(b));
    return r;
}
__device__ __forceinline__ void unpack2(unsigned long long v, float& a, float& b) {
    asm("mov.b64 {%0, %1}, %2;" : "=f"(a), "=f"(b) : "l"(v));
}
__device__ __forceinline__ unsigned long long fma2(unsigned long long a,
                                                   unsigned long long b,
                                                   unsigned long long c) {
    unsigned long long r;
    asm("fma.rn.f32x2 %0, %1, %2, %3;" : "=l"(r) : "l"(a), "l"(b), "l"(c));
    return r;
}
__device__ __forceinline__ void cp_async16(unsigned int smem_addr, const void* gptr) {
    asm volatile("cp.async.cg.shared.global [%0], [%1], 16;"
                 :: "r"(smem_addr), "l"(gptr) : "memory");
}
__device__ __forceinline__ void cp_async_commit_wait0() {
    asm volatile("cp.async.commit_group;\n\tcp.async.wait_group 0;" ::: "memory");
}

// ============================================================
// K1: feat = h @ W_p (stored fp16) ; el/er attn dots (fp32)
// warp = 8 nodes, lane = 4 consecutive cols
// ============================================================
__global__ void __launch_bounds__(256) feat_kernel(
                            const float* __restrict__ h,
                            const float* __restrict__ fc_w,
                            const float* __restrict__ attn_l,
                            const float* __restrict__ attn_r) {
    int p = blockIdx.y;
    const ulonglong2* W2 = (const ulonglong2*)(fc_w + (size_t)p * INF * HF);
    int warpId = threadIdx.x >> 5;
    int lane = threadIdx.x & 31;
    int gw = blockIdx.x * 8 + warpId;
    int n0 = gw * 8;                    // Nn % 8 == 0
    if (n0 >= Nn) return;

    const float4* h4 = (const float4*)h;

    unsigned long long acc[8][2];
    #pragma unroll
    for (int r = 0; r < 8; r++) { acc[r][0] = 0ull; acc[r][1] = 0ull; }

    for (int k4 = 0; k4 < 32; k4++) {
        float4 hv0 = __ldg(h4 + (size_t)(n0 + 0) * 32 + k4);
        float4 hv1 = __ldg(h4 + (size_t)(n0 + 1) * 32 + k4);
        float4 hv2 = __ldg(h4 + (size_t)(n0 + 2) * 32 + k4);
        float4 hv3 = __ldg(h4 + (size_t)(n0 + 3) * 32 + k4);
        float4 hv4 = __ldg(h4 + (size_t)(n0 + 4) * 32 + k4);
        float4 hv5 = __ldg(h4 + (size_t)(n0 + 5) * 32 + k4);
        float4 hv6 = __ldg(h4 + (size_t)(n0 + 6) * 32 + k4);
        float4 hv7 = __ldg(h4 + (size_t)(n0 + 7) * 32 + k4);
        float hs[8][4] = {
            {hv0.x, hv0.y, hv0.z, hv0.w}, {hv1.x, hv1.y, hv1.z, hv1.w},
            {hv2.x, hv2.y, hv2.z, hv2.w}, {hv3.x, hv3.y, hv3.z, hv3.w},
            {hv4.x, hv4.y, hv4.z, hv4.w}, {hv5.x, hv5.y, hv5.z, hv5.w},
            {hv6.x, hv6.y, hv6.z, hv6.w}, {hv7.x, hv7.y, hv7.z, hv7.w}};
        #pragma unroll
        for (int kk = 0; kk < 4; kk++) {
            ulonglong2 wv = W2[(size_t)(k4 * 4 + kk) * 32 + lane];
            #pragma unroll
            for (int r = 0; r < 8; r++) {
                unsigned long long pr = pack2(hs[r][kk], hs[r][kk]);
                acc[r][0] = fma2(pr, wv.x, acc[r][0]);
                acc[r][1] = fma2(pr, wv.y, acc[r][1]);
            }
        }
    }

    float4 accs[8];
    #pragma unroll
    for (int r = 0; r < 8; r++) {
        unpack2(acc[r][0], accs[r].x, accs[r].y);
        unpack2(acc[r][1], accs[r].z, accs[r].w);
    }

    uint2* feath = (uint2*)g_feat_h;
    #pragma unroll
    for (int r = 0; r < 8; r++) {
        __half2 a01 = __floats2half2_rn(accs[r].x, accs[r].y);
        __half2 a23 = __floats2half2_rn(accs[r].z, accs[r].w);
        uint2 st;
        st.x = *reinterpret_cast<unsigned int*>(&a01);
        st.y = *reinterpret_cast<unsigned int*>(&a23);
        feath[((size_t)p * Nn + n0 + r) * 32 + lane] = st;
    }

    float4 al4 = ((const float4*)(attn_l + (size_t)p * HF))[lane];
    float4 ar4 = ((const float4*)(attn_r + (size_t)p * HF))[lane];
    int head = lane >> 3;

    #pragma unroll
    for (int j = 0; j < 8; j++) {
        float pl = accs[j].x * al4.x + accs[j].y * al4.y + accs[j].z * al4.z + accs[j].w * al4.w;
        float pr = accs[j].x * ar4.x + accs[j].y * ar4.y + accs[j].z * ar4.z + accs[j].w * ar4.w;
        #pragma unroll
        for (int off = 4; off >= 1; off >>= 1) {
            pl += __shfl_xor_sync(0xffffffffu, pl, off);
            pr += __shfl_xor_sync(0xffffffffu, pr, off);
        }
        if ((lane & 7) == 0) {
            g_el[((size_t)p * Nn + n0 + j) * Hh + head] = pl;
            g_er[((size_t)p * Nn + n0 + j) * Hh + head] = pr;
        }
    }
}

// ============================================================
// CSR build: histogram -> scan -> scatter (src ids only)
// ============================================================
__global__ void hist_kernel(const int* __restrict__ dst) {
    int p = blockIdx.y;
    int e = blockIdx.x * 256 + threadIdx.x;
    if (e >= Ee) return;
    atomicAdd(&g_deg[p * Nn + __ldg(dst + (size_t)p * Ee + e)], 1);
}

__global__ void scan1_kernel() {
    __shared__ int wsum[32];
    int tid = threadIdx.x, lane = tid & 31, wid = tid >> 5;
    int i = blockIdx.x * 1024 + tid;
    int v = (i < TOT) ? g_deg[i] : 0;
    int x = v;
    #pragma unroll
    for (int o = 1; o < 32; o <<= 1) {
        int y = __shfl_up_sync(0xffffffffu, x, o);
        if (lane >= o) x += y;
    }
    if (lane == 31) wsum[wid] = x;
    __syncthreads();
    if (wid == 0) {
        int s = wsum[lane];
        #pragma unroll
        for (int o = 1; o < 32; o <<= 1) {
            int y = __shfl_up_sync(0xffffffffu, s, o);
            if (lane >= o) s += y;
        }
        wsum[lane] = s;
    }
    __syncthreads();
    int woff = (wid == 0) ? 0 : wsum[wid - 1];
    if (i < TOT) g_off[i] = woff + x - v;
    if (tid == 1023) g_bsum[blockIdx.x] = wsum[31];
}

__global__ void scan23_kernel() {
    __shared__ int sh_scan[SCAN_B];
    if (threadIdx.x < 32) {
        int lane = threadIdx.x;
        int v[4];
        int s = 0;
        #pragma unroll
        for (int j = 0; j < 4; j++) {
            int idx = lane * 4 + j;
            int t = (idx < SCAN_B) ? g_bsum[idx] : 0;
            v[j] = s;
            s += t;
        }
        int x = s;
        #pragma unroll
        for (int o = 1; o < 32; o <<= 1) {
            int y = __shfl_up_sync(0xffffffffu, x, o);
            if (lane >= o) x += y;
        }
        int excl = x - s;
        #pragma unroll
        for (int j = 0; j < 4; j++) {
            int idx = lane * 4 + j;
            if (idx < SCAN_B) sh_scan[idx] = excl + v[j];
        }
    }
    __syncthreads();
    int i = blockIdx.x * 1024 + threadIdx.x;
    if (i < TOT) {
        int o = g_off[i] + sh_scan[blockIdx.x];
        g_off[i] = o;
        g_cur[i] = o;
    }
}

__global__ void scatter_kernel(const int* __restrict__ src,
                               const int* __restrict__ dst) {
    int p = blockIdx.y;
    int e = blockIdx.x * 256 + threadIdx.x;
    if (e >= Ee) return;
    size_t idx = (size_t)p * Ee + e;
    int d = __ldg(dst + idx);
    int pos = atomicAdd(&g_cur[p * Nn + d], 1);
    g_csr_src[pos] = __ldg(src + idx);
}

// ============================================================
// K4: CSR aggregation — warp per dst node, cp.async staging.
// 16-edge chunks, 8 warps/block, 34 KB smem, 48 warps/SM.
// Phase 2: ONE lane per edge loads el as float4 (1 LDG.128 =
// 1 sector vs 4 scattered 4B loads), computes all 4 head
// weights, stores with one STS.128. 4x fewer weight sectors.
// ============================================================
__global__ void __launch_bounds__(256) agg_kernel() {
    __shared__ __align__(16) unsigned char s_feat[8][CHUNK * 256]; // 32 KB
    __shared__ __align__(16) float s_w[8][CHUNK * 4];              // 2 KB

    int warpId = threadIdx.x >> 5;
    int lane = threadIdx.x & 31;
    int w = blockIdx.x * 8 + warpId;
    if (w >= TOT) return;
    int p = (w >= Nn) ? 1 : 0;
    size_t pbase = (size_t)p * Nn;

    int beg = g_off[w];
    int deg = g_deg[w];
    int head = lane >> 3;
    float4 er4 = __ldg(((const float4*)g_er) + w);   // all 4 head logits of dst

    const char* featg = (const char*)g_feat_h;
    unsigned int feat_s_base = (unsigned int)__cvta_generic_to_shared(&s_feat[warpId][0]);
    float* w_s = &s_w[warpId][0];

    unsigned long long a00 = 0ull, a01 = 0ull;
    unsigned long long a10 = 0ull, a11 = 0ull;
    float den = 0.f;

    for (int j = 0; j < deg; j += CHUNK) {
        int cnt = min(CHUNK, deg - j);
        // lane < CHUNK holds edge (j+lane)'s src id
        int s = g_csr_src[beg + j + min(lane, cnt - 1)];

        // phase 1: issue cp.async for all cnt feat rows (2 rows / step)
        int nsteps = (cnt + 1) >> 1;
        int sub = lane >> 4;          // 0 or 1: which of the 2 rows
        int boff = (lane & 15) * 16;  // byte offset within row
        #pragma unroll 4
        for (int r2 = 0; r2 < nsteps; r2++) {
            int row = r2 * 2 + sub;
            int sk = __shfl_sync(0xffffffffu, s, min(row, cnt - 1));
            if (row < cnt)
                cp_async16(feat_s_base + row * 256 + boff,
                           featg + ((pbase + sk) << 8) + boff);
        }

        // phase 2 (overlaps in-flight copies): one lane per edge,
        // all 4 head weights from a single float4 el load.
        if (lane < cnt) {
            float4 el4 = __ldg(((const float4*)g_el) + pbase + s);
            float v0 = el4.x + er4.x; v0 = v0 > 0.f ? v0 : 0.2f * v0;
            float v1 = el4.y + er4.y; v1 = v1 > 0.f ? v1 : 0.2f * v1;
            float v2 = el4.z + er4.z; v2 = v2 > 0.f ? v2 : 0.2f * v2;
            float v3 = el4.w + er4.w; v3 = v3 > 0.f ? v3 : 0.2f * v3;
            float4 wv4;
            wv4.x = __expf(v0); wv4.y = __expf(v1);
            wv4.z = __expf(v2); wv4.w = __expf(v3);
            ((float4*)w_s)[lane] = wv4;       // [edge][head] layout
        }

        cp_async_commit_wait0();
        __syncwarp();

        // phase 3: consume from smem
        const uint2* fs = (const uint2*)&s_feat[warpId][0];
        int k = 0;
        for (; k + 4 <= cnt; k += 4) {
            float w0 = w_s[(k + 0) * 4 + head];
            float w1 = w_s[(k + 1) * 4 + head];
            float w2 = w_s[(k + 2) * 4 + head];
            float w3 = w_s[(k + 3) * 4 + head];
            uint2 f0 = fs[(k + 0) * 32 + lane];
            uint2 f1 = fs[(k + 1) * 32 + lane];
            uint2 f2 = fs[(k + 2) * 32 + lane];
            uint2 f3 = fs[(k + 3) * 32 + lane];
            float2 f0a = __half22float2(*reinterpret_cast<__half2*>(&f0.x));
            float2 f0b = __half22float2(*reinterpret_cast<__half2*>(&f0.y));
            float2 f1a = __half22float2(*reinterpret_cast<__half2*>(&f1.x));
            float2 f1b = __half22float2(*reinterpret_cast<__half2*>(&f1.y));
            float2 f2a = __half22float2(*reinterpret_cast<__half2*>(&f2.x));
            float2 f2b = __half22float2(*reinterpret_cast<__half2*>(&f2.y));
            float2 f3a = __half22float2(*reinterpret_cast<__half2*>(&f3.x));
            float2 f3b = __half22float2(*reinterpret_cast<__half2*>(&f3.y));
            unsigned long long p0 = pack2(w0, w0);
            unsigned long long p1 = pack2(w1, w1);
            unsigned long long p2 = pack2(w2, w2);
            unsigned long long p3 = pack2(w3, w3);
            a00 = fma2(p0, pack2(f0a.x, f0a.y), a00);
            a01 = fma2(p0, pack2(f0b.x, f0b.y), a01);
            a10 = fma2(p1, pack2(f1a.x, f1a.y), a10);
            a11 = fma2(p1, pack2(f1b.x, f1b.y), a11);
            a00 = fma2(p2, pack2(f2a.x, f2a.y), a00);
            a01 = fma2(p2, pack2(f2b.x, f2b.y), a01);
            a10 = fma2(p3, pack2(f3a.x, f3a.y), a10);
            a11 = fma2(p3, pack2(f3b.x, f3b.y), a11);
            den += (w0 + w1) + (w2 + w3);
        }
        for (; k < cnt; k++) {
            float w0 = w_s[k * 4 + head];
            uint2 f0 = fs[k * 32 + lane];
            float2 f0a = __half22float2(*reinterpret_cast<__half2*>(&f0.x));
            float2 f0b = __half22float2(*reinterpret_cast<__half2*>(&f0.y));
            unsigned long long p0 = pack2(w0, w0);
            a00 = fma2(p0, pack2(f0a.x, f0a.y), a00);
            a01 = fma2(p0, pack2(f0b.x, f0b.y), a01);
            den += w0;
        }
        __syncwarp();   // all lanes done reading before next chunk overwrites
    }

    float ax0, ay0, az0, aw0, ax1, ay1, az1, aw1;
    unpack2(a00, ax0, ay0); unpack2(a01, az0, aw0);
    unpack2(a10, ax1, ay1); unpack2(a11, az1, aw1);
    float inv = 1.0f / fmaxf(den, 1e-9f);
    float4 r;
    r.x = (ax0 + ax1) * inv;
    r.y = (ay0 + ay1) * inv;
    r.z = (az0 + az1) * inv;
    r.w = (aw0 + aw1) * inv;
    ((float4*)g_out)[(size_t)w * 32 + lane] = r;
}

// ============================================================
// K5: semantic attention scores (round-10 4-row form)
// ============================================================
__global__ void sem_kernel(const float* __restrict__ bias,
                           const float* __restrict__ sem_w1,
                           const float* __restrict__ sem_b1,
                           const float* __restrict__ sem_w2) {
    __shared__ __align__(16) float z_sh[32 * HF];
    int p = blockIdx.y;
    int base = blockIdx.x * 32;

    for (int i = threadIdx.x; i < 32 * HF; i += 256) {
        int node = base + (i >> 7);
        int c = i & 127;
        float z = 0.f;
        if (node < Nn) {
            float raw = g_out[((size_t)p * Nn + node) * HF + c] + bias[(size_t)p * HF + c];
            z = raw > 0.f ? raw : (__expf(raw) - 1.0f);
        }
        z_sh[i] = z;
    }
    __syncthreads();

    int warpId = threadIdx.x >> 5;
    int lane = threadIdx.x & 31;
    const ulonglong2* W2 = (const ulonglong2*)sem_w1;
    const float4* z4 = (const float4*)z_sh;

    unsigned long long acc[4][2];
    #pragma unroll
    for (int r = 0; r < 4; r++) { acc[r][0] = 0ull; acc[r][1] = 0ull; }

    for (int k4 = 0; k4 < 32; k4++) {
        float4 zv0 = z4[(warpId * 4 + 0) * 32 + k4];
        float4 zv1 = z4[(warpId * 4 + 1) * 32 + k4];
        float4 zv2 = z4[(warpId * 4 + 2) * 32 + k4];
        float4 zv3 = z4[(warpId * 4 + 3) * 32 + k4];
        float z0v[4] = {zv0.x, zv0.y, zv0.z, zv0.w};
        float z1v[4] = {zv1.x, zv1.y, zv1.z, zv1.w};
        float z2v[4] = {zv2.x, zv2.y, zv2.z, zv2.w};
        float z3v[4] = {zv3.x, zv3.y, zv3.z, zv3.w};
        #pragma unroll
        for (int kk = 0; kk < 4; kk++) {
            ulonglong2 wv = W2[(size_t)(k4 * 4 + kk) * 32 + lane];
            unsigned long long p0 = pack2(z0v[kk], z0v[kk]);
            unsigned long long p1 = pack2(z1v[kk], z1v[kk]);
            unsigned long long p2 = pack2(z2v[kk], z2v[kk]);
            unsigned long long p3 = pack2(z3v[kk], z3v[kk]);
            acc[0][0] = fma2(p0, wv.x, acc[0][0]); acc[0][1] = fma2(p0, wv.y, acc[0][1]);
            acc[1][0] = fma2(p1, wv.x, acc[1][0]); acc[1][1] = fma2(p1, wv.y, acc[1][1]);
            acc[2][0] = fma2(p2, wv.x, acc[2][0]); acc[2][1] = fma2(p2, wv.y, acc[2][1]);
            acc[3][0] = fma2(p3, wv.x, acc[3][0]); acc[3][1] = fma2(p3, wv.y, acc[3][1]);
        }
    }

    float4 b14 = ((const float4*)sem_b1)[lane];
    float4 w24 = ((const float4*)sem_w2)[lane];

    float total = 0.f;
    #pragma unroll
    for (int j = 0; j < 4; j++) {
        float4 a;
        unpack2(acc[j][0], a.x, a.y);
        unpack2(acc[j][1], a.z, a.w);
        float cj = tanhf(a.x + b14.x) * w24.x
                 + tanhf(a.y + b14.y) * w24.y
                 + tanhf(a.z + b14.z) * w24.z
                 + tanhf(a.w + b14.w) * w24.w;
        #pragma unroll
        for (int off = 16; off >= 1; off >>= 1)
            cj += __shfl_xor_sync(0xffffffffu, cj, off);
        int node = base + warpId * 4 + j;
        if (node < Nn) total += cj;
    }
    if (lane == 0) atomicAdd(&g_wsum[p], total);
}

// ============================================================
// K6: combine with semantic softmax
// ============================================================
__global__ void final_kernel(const float* __restrict__ bias,
                             float* __restrict__ out) {
    size_t i = (size_t)blockIdx.x * 256 + threadIdx.x;
    if (i >= (size_t)Nn * 32) return;
    float w0 = g_wsum[0] * (1.0f / Nn);
    float w1 = g_wsum[1] * (1.0f / Nn);
    float m = fmaxf(w0, w1);
    float e0 = __expf(w0 - m), e1 = __expf(w1 - m);
    float inv = 1.0f / (e0 + e1);
    float b0 = e0 * inv, b1 = e1 * inv;

    int c4 = (int)(i & 31);
    float4 r0 = ((const float4*)g_out)[i];
    float4 r1 = ((const float4*)g_out)[(size_t)Nn * 32 + i];
    float4 bi0 = ((const float4*)bias)[c4];
    float4 bi1 = ((const float4*)bias)[32 + c4];

    float4 res;
    float v;
    v = r0.x + bi0.x; v = v > 0.f ? v : (__expf(v) - 1.f); res.x = b0 * v;
    v = r0.y + bi0.y; v = v > 0.f ? v : (__expf(v) - 1.f); res.y = b0 * v;
    v = r0.z + bi0.z; v = v > 0.f ? v : (__expf(v) - 1.f); res.z = b0 * v;
    v = r0.w + bi0.w; v = v > 0.f ? v : (__expf(v) - 1.f); res.w = b0 * v;
    v = r1.x + bi1.x; v = v > 0.f ? v : (__expf(v) - 1.f); res.x += b1 * v;
    v = r1.y + bi1.y; v = v > 0.f ? v : (__expf(v) - 1.f); res.y += b1 * v;
    v = r1.z + bi1.z; v = v > 0.f ? v : (__expf(v) - 1.f); res.z += b1 * v;
    v = r1.w + bi1.w; v = v > 0.f ? v : (__expf(v) - 1.f); res.w += b1 * v;

    ((float4*)out)[i] = res;
}

extern "C" void kernel_launch(void* const* d_in, const int* in_sizes, int n_in,
                              void* d_out, int out_size) {
    const float* h      = (const float*)d_in[0];
    const int*   src    = (const int*)  d_in[1];
    const int*   dst    = (const int*)  d_in[2];
    const float* fc_w   = (const float*)d_in[3];
    const float* attn_l = (const float*)d_in[4];
    const float* attn_r = (const float*)d_in[5];
    const float* bias   = (const float*)d_in[6];
    const float* sem_w1 = (const float*)d_in[7];
    const float* sem_b1 = (const float*)d_in[8];
    const float* sem_w2 = (const float*)d_in[9];
    float* out = (float*)d_out;

    static cudaStream_t s2 = nullptr;
    static cudaEvent_t evFork = nullptr, evJoin = nullptr;
    if (s2 == nullptr) {
        cudaStreamCreateWithFlags(&s2, cudaStreamNonBlocking);
        cudaEventCreateWithFlags(&evFork, cudaEventDisableTiming);
        cudaEventCreateWithFlags(&evJoin, cudaEventDisableTiming);
    }

    void *p_deg, *p_wsum;
    cudaGetSymbolAddress(&p_deg, g_deg);
    cudaGetSymbolAddress(&p_wsum, g_wsum);

    // fork: full CSR build (hist+scan+scatter) on s2, feat GEMM on main
    cudaEventRecord(evFork, 0);
    cudaStreamWaitEvent(s2, evFork, 0);

    // --- branch B (s2): histogram + offsets + scatter ---
    cudaMemsetAsync(p_deg, 0, sizeof(int) * TOT, s2);
    dim3 gEdge((Ee + 255) / 256, Pp);
    hist_kernel<<<gEdge, 256, 0, s2>>>(dst);
    scan1_kernel<<<SCAN_B, 1024, 0, s2>>>();
    scan23_kernel<<<SCAN_B, 1024, 0, s2>>>();
    scatter_kernel<<<gEdge, 256, 0, s2>>>(src, dst);
    cudaEventRecord(evJoin, s2);

    // --- branch A (main): features + attn dots ---
    cudaMemsetAsync(p_wsum, 0, sizeof(float) * Pp);
    dim3 gFeat((Nn / 8 + 7) / 8, Pp);
    feat_kernel<<<gFeat, 256>>>(h, fc_w, attn_l, attn_r);

    // join: agg needs CSR (s2) and feat/el/er (main)
    cudaStreamWaitEvent(0, evJoin, 0);

    agg_kernel<<<(TOT + 7) / 8, 256>>>();

    dim3 gSem((Nn + 31) / 32, Pp);
    sem_kernel<<<gSem, 256>>>(bias, sem_w1, sem_b1, sem_w2);

    final_kernel<<<((size_t)Nn * 32 + 255) / 256, 256>>>(bias, out);
}

// round 17
// speedup vs baseline: 1.4435x; 1.0371x over previous
#include <cuda_runtime.h>
#include <cuda_bf16.h>
#include <cuda_fp16.h>
#include <math.h>

#define Nn 50000
#define Ee 800000
#define Pp 2
#define Hh 4
#define Ff 32
#define HF 128
#define INF 128
#define TOT (Pp * Nn)          // 100000 destination slots
#define SCAN_B 98              // ceil(TOT/1024)
#define CHUNK 16               // agg staging chunk (edges)

// ---- scratch (device globals; allocation-free) ----
__device__ __half g_feat_h[(size_t)Pp * Nn * HF]; // 25.6 MB (gather path)
__device__ float g_el[(size_t)Pp * Nn * Hh];
__device__ float g_er[(size_t)Pp * Nn * Hh];
__device__ __half g_out_h[(size_t)Pp * Nn * HF];  // 25.6 MB (fp16 intermediate)
__device__ float g_wsum[Pp];
__device__ int   g_deg[TOT];
__device__ int   g_off[TOT];
__device__ int   g_cur[TOT];
__device__ int   g_bsum[SCAN_B];
__device__ int   g_csr_src[(size_t)Pp * Ee + 32];     // src ids, CSR order

// ---- packed fp32x2 helpers (Blackwell) ----
__device__ __forceinline__ unsigned long long pack2(float a, float b) {
    unsigned long long r;
    asm("mov.b64 %0, {%1, %2};" : "=l"(r) : "f"(a), "f"(b));
    return r;
}
__device__ __forceinline__ void unpack2(unsigned long long v, float& a, float& b) {
    asm("mov.b64 {%0, %1}, %2;" : "=f"(a), "=f"(b) : "l"(v));
}
__device__ __forceinline__ unsigned long long fma2(unsigned long long a,
                                                   unsigned long long b,
                                                   unsigned long long c) {
    unsigned long long r;
    asm("fma.rn.f32x2 %0, %1, %2, %3;" : "=l"(r) : "l"(a), "l"(b), "l"(c));
    return r;
}
__device__ __forceinline__ void cp_async16(unsigned int smem_addr, const void* gptr) {
    asm volatile("cp.async.cg.shared.global [%0], [%1], 16;"
                 :: "r"(smem_addr), "l"(gptr) : "memory");
}
__device__ __forceinline__ void cp_async_commit_wait0() {
    asm volatile("cp.async.commit_group;\n\tcp.async.wait_group 0;" ::: "memory");
}

// ============================================================
// K1: feat = h @ W_p (stored fp16) ; el/er attn dots (fp32)
// warp = 8 nodes, lane = 4 consecutive cols
// ============================================================
__global__ void __launch_bounds__(256) feat_kernel(
                            const float* __restrict__ h,
                            const float* __restrict__ fc_w,
                            const float* __restrict__ attn_l,
                            const float* __restrict__ attn_r) {
    int p = blockIdx.y;
    const ulonglong2* W2 = (const ulonglong2*)(fc_w + (size_t)p * INF * HF);
    int warpId = threadIdx.x >> 5;
    int lane = threadIdx.x & 31;
    int gw = blockIdx.x * 8 + warpId;
    int n0 = gw * 8;                    // Nn % 8 == 0
    if (n0 >= Nn) return;

    const float4* h4 = (const float4*)h;

    unsigned long long acc[8][2];
    #pragma unroll
    for (int r = 0; r < 8; r++) { acc[r][0] = 0ull; acc[r][1] = 0ull; }

    for (int k4 = 0; k4 < 32; k4++) {
        float4 hv0 = __ldg(h4 + (size_t)(n0 + 0) * 32 + k4);
        float4 hv1 = __ldg(h4 + (size_t)(n0 + 1) * 32 + k4);
        float4 hv2 = __ldg(h4 + (size_t)(n0 + 2) * 32 + k4);
        float4 hv3 = __ldg(h4 + (size_t)(n0 + 3) * 32 + k4);
        float4 hv4 = __ldg(h4 + (size_t)(n0 + 4) * 32 + k4);
        float4 hv5 = __ldg(h4 + (size_t)(n0 + 5) * 32 + k4);
        float4 hv6 = __ldg(h4 + (size_t)(n0 + 6) * 32 + k4);
        float4 hv7 = __ldg(h4 + (size_t)(n0 + 7) * 32 + k4);
        float hs[8][4] = {
            {hv0.x, hv0.y, hv0.z, hv0.w}, {hv1.x, hv1.y, hv1.z, hv1.w},
            {hv2.x, hv2.y, hv2.z, hv2.w}, {hv3.x, hv3.y, hv3.z, hv3.w},
            {hv4.x, hv4.y, hv4.z, hv4.w}, {hv5.x, hv5.y, hv5.z, hv5.w},
            {hv6.x, hv6.y, hv6.z, hv6.w}, {hv7.x, hv7.y, hv7.z, hv7.w}};
        #pragma unroll
        for (int kk = 0; kk < 4; kk++) {
            ulonglong2 wv = W2[(size_t)(k4 * 4 + kk) * 32 + lane];
            #pragma unroll
            for (int r = 0; r < 8; r++) {
                unsigned long long pr = pack2(hs[r][kk], hs[r][kk]);
                acc[r][0] = fma2(pr, wv.x, acc[r][0]);
                acc[r][1] = fma2(pr, wv.y, acc[r][1]);
            }
        }
    }

    float4 accs[8];
    #pragma unroll
    for (int r = 0; r < 8; r++) {
        unpack2(acc[r][0], accs[r].x, accs[r].y);
        unpack2(acc[r][1], accs[r].z, accs[r].w);
    }

    uint2* feath = (uint2*)g_feat_h;
    #pragma unroll
    for (int r = 0; r < 8; r++) {
        __half2 a01 = __floats2half2_rn(accs[r].x, accs[r].y);
        __half2 a23 = __floats2half2_rn(accs[r].z, accs[r].w);
        uint2 st;
        st.x = *reinterpret_cast<unsigned int*>(&a01);
        st.y = *reinterpret_cast<unsigned int*>(&a23);
        feath[((size_t)p * Nn + n0 + r) * 32 + lane] = st;
    }

    float4 al4 = ((const float4*)(attn_l + (size_t)p * HF))[lane];
    float4 ar4 = ((const float4*)(attn_r + (size_t)p * HF))[lane];
    int head = lane >> 3;

    #pragma unroll
    for (int j = 0; j < 8; j++) {
        float pl = accs[j].x * al4.x + accs[j].y * al4.y + accs[j].z * al4.z + accs[j].w * al4.w;
        float pr = accs[j].x * ar4.x + accs[j].y * ar4.y + accs[j].z * ar4.z + accs[j].w * ar4.w;
        #pragma unroll
        for (int off = 4; off >= 1; off >>= 1) {
            pl += __shfl_xor_sync(0xffffffffu, pl, off);
            pr += __shfl_xor_sync(0xffffffffu, pr, off);
        }
        if ((lane & 7) == 0) {
            g_el[((size_t)p * Nn + n0 + j) * Hh + head] = pl;
            g_er[((size_t)p * Nn + n0 + j) * Hh + head] = pr;
        }
    }
}

// ============================================================
// CSR build: histogram -> scan -> scatter (src ids only)
// ============================================================
__global__ void hist_kernel(const int* __restrict__ dst) {
    int p = blockIdx.y;
    int e = blockIdx.x * 256 + threadIdx.x;
    if (e >= Ee) return;
    atomicAdd(&g_deg[p * Nn + __ldg(dst + (size_t)p * Ee + e)], 1);
}

__global__ void scan1_kernel() {
    __shared__ int wsum[32];
    int tid = threadIdx.x, lane = tid & 31, wid = tid >> 5;
    int i = blockIdx.x * 1024 + tid;
    int v = (i < TOT) ? g_deg[i] : 0;
    int x = v;
    #pragma unroll
    for (int o = 1; o < 32; o <<= 1) {
        int y = __shfl_up_sync(0xffffffffu, x, o);
        if (lane >= o) x += y;
    }
    if (lane == 31) wsum[wid] = x;
    __syncthreads();
    if (wid == 0) {
        int s = wsum[lane];
        #pragma unroll
        for (int o = 1; o < 32; o <<= 1) {
            int y = __shfl_up_sync(0xffffffffu, s, o);
            if (lane >= o) s += y;
        }
        wsum[lane] = s;
    }
    __syncthreads();
    int woff = (wid == 0) ? 0 : wsum[wid - 1];
    if (i < TOT) g_off[i] = woff + x - v;
    if (tid == 1023) g_bsum[blockIdx.x] = wsum[31];
}

__global__ void scan23_kernel() {
    __shared__ int sh_scan[SCAN_B];
    if (threadIdx.x < 32) {
        int lane = threadIdx.x;
        int v[4];
        int s = 0;
        #pragma unroll
        for (int j = 0; j < 4; j++) {
            int idx = lane * 4 + j;
            int t = (idx < SCAN_B) ? g_bsum[idx] : 0;
            v[j] = s;
            s += t;
        }
        int x = s;
        #pragma unroll
        for (int o = 1; o < 32; o <<= 1) {
            int y = __shfl_up_sync(0xffffffffu, x, o);
            if (lane >= o) x += y;
        }
        int excl = x - s;
        #pragma unroll
        for (int j = 0; j < 4; j++) {
            int idx = lane * 4 + j;
            if (idx < SCAN_B) sh_scan[idx] = excl + v[j];
        }
    }
    __syncthreads();
    int i = blockIdx.x * 1024 + threadIdx.x;
    if (i < TOT) {
        int o = g_off[i] + sh_scan[blockIdx.x];
        g_off[i] = o;
        g_cur[i] = o;
    }
}

__global__ void scatter_kernel(const int* __restrict__ src,
                               const int* __restrict__ dst) {
    int p = blockIdx.y;
    int e = blockIdx.x * 256 + threadIdx.x;
    if (e >= Ee) return;
    size_t idx = (size_t)p * Ee + e;
    int d = __ldg(dst + idx);
    int pos = atomicAdd(&g_cur[p * Nn + d], 1);
    g_csr_src[pos] = __ldg(src + idx);
}

// ============================================================
// K4: CSR aggregation — warp per dst node, cp.async staging.
// 16-edge chunks, 8 warps/block, 34 KB smem, 48 warps/SM.
// (round-10 proven form; fp16 output store)
// ============================================================
__global__ void __launch_bounds__(256) agg_kernel() {
    __shared__ __align__(16) unsigned char s_feat[8][CHUNK * 256]; // 32 KB
    __shared__ float s_w[8][CHUNK * 4];                            // 2 KB

    int warpId = threadIdx.x >> 5;
    int lane = threadIdx.x & 31;
    int w = blockIdx.x * 8 + warpId;
    if (w >= TOT) return;
    int p = (w >= Nn) ? 1 : 0;
    size_t pbase = (size_t)p * Nn;

    int beg = g_off[w];
    int deg = g_deg[w];
    int head = lane >> 3;
    float erd = g_er[(size_t)w * Hh + head];

    const char* featg = (const char*)g_feat_h;
    unsigned int feat_s_base = (unsigned int)__cvta_generic_to_shared(&s_feat[warpId][0]);
    float* w_s = &s_w[warpId][0];

    unsigned long long a00 = 0ull, a01 = 0ull;
    unsigned long long a10 = 0ull, a11 = 0ull;
    float den = 0.f;

    for (int j = 0; j < deg; j += CHUNK) {
        int cnt = min(CHUNK, deg - j);
        // lane < CHUNK holds edge (j+lane)'s src id
        int s = g_csr_src[beg + j + min(lane, cnt - 1)];

        // phase 1: issue cp.async for all cnt feat rows (2 rows / step)
        int nsteps = (cnt + 1) >> 1;
        int sub = lane >> 4;          // 0 or 1: which of the 2 rows
        int boff = (lane & 15) * 16;  // byte offset within row
        #pragma unroll 8
        for (int r2 = 0; r2 < nsteps; r2++) {
            int row = r2 * 2 + sub;
            int sk = __shfl_sync(0xffffffffu, s, min(row, cnt - 1));
            if (row < cnt)
                cp_async16(feat_s_base + row * 256 + boff,
                           featg + ((pbase + sk) << 8) + boff);
        }

        // phase 2 (overlaps in-flight copies): weights for CHUNKx4
        // lane covers edge (q*8 + lane&7), head (lane>>3); layout [k][head]
        #pragma unroll
        for (int q = 0; q < CHUNK / 8; q++) {
            int ek = q * 8 + (lane & 7);
            int sk = __shfl_sync(0xffffffffu, s, min(ek, cnt - 1));
            float el = __ldg(g_el + (pbase + sk) * Hh + head);
            float v = el + erd; v = v > 0.f ? v : 0.2f * v;
            w_s[ek * 4 + head] = __expf(v);
        }

        cp_async_commit_wait0();
        __syncwarp();

        // phase 3: consume from smem
        const uint2* fs = (const uint2*)&s_feat[warpId][0];
        int k = 0;
        for (; k + 4 <= cnt; k += 4) {
            float w0 = w_s[(k + 0) * 4 + head];
            float w1 = w_s[(k + 1) * 4 + head];
            float w2 = w_s[(k + 2) * 4 + head];
            float w3 = w_s[(k + 3) * 4 + head];
            uint2 f0 = fs[(k + 0) * 32 + lane];
            uint2 f1 = fs[(k + 1) * 32 + lane];
            uint2 f2 = fs[(k + 2) * 32 + lane];
            uint2 f3 = fs[(k + 3) * 32 + lane];
            float2 f0a = __half22float2(*reinterpret_cast<__half2*>(&f0.x));
            float2 f0b = __half22float2(*reinterpret_cast<__half2*>(&f0.y));
            float2 f1a = __half22float2(*reinterpret_cast<__half2*>(&f1.x));
            float2 f1b = __half22float2(*reinterpret_cast<__half2*>(&f1.y));
            float2 f2a = __half22float2(*reinterpret_cast<__half2*>(&f2.x));
            float2 f2b = __half22float2(*reinterpret_cast<__half2*>(&f2.y));
            float2 f3a = __half22float2(*reinterpret_cast<__half2*>(&f3.x));
            float2 f3b = __half22float2(*reinterpret_cast<__half2*>(&f3.y));
            unsigned long long p0 = pack2(w0, w0);
            unsigned long long p1 = pack2(w1, w1);
            unsigned long long p2 = pack2(w2, w2);
            unsigned long long p3 = pack2(w3, w3);
            a00 = fma2(p0, pack2(f0a.x, f0a.y), a00);
            a01 = fma2(p0, pack2(f0b.x, f0b.y), a01);
            a10 = fma2(p1, pack2(f1a.x, f1a.y), a10);
            a11 = fma2(p1, pack2(f1b.x, f1b.y), a11);
            a00 = fma2(p2, pack2(f2a.x, f2a.y), a00);
            a01 = fma2(p2, pack2(f2b.x, f2b.y), a01);
            a10 = fma2(p3, pack2(f3a.x, f3a.y), a10);
            a11 = fma2(p3, pack2(f3b.x, f3b.y), a11);
            den += (w0 + w1) + (w2 + w3);
        }
        for (; k < cnt; k++) {
            float w0 = w_s[k * 4 + head];
            uint2 f0 = fs[k * 32 + lane];
            float2 f0a = __half22float2(*reinterpret_cast<__half2*>(&f0.x));
            float2 f0b = __half22float2(*reinterpret_cast<__half2*>(&f0.y));
            unsigned long long p0 = pack2(w0, w0);
            a00 = fma2(p0, pack2(f0a.x, f0a.y), a00);
            a01 = fma2(p0, pack2(f0b.x, f0b.y), a01);
            den += w0;
        }
        __syncwarp();   // all lanes done reading before next chunk overwrites
    }

    float ax0, ay0, az0, aw0, ax1, ay1, az1, aw1;
    unpack2(a00, ax0, ay0); unpack2(a01, az0, aw0);
    unpack2(a10, ax1, ay1); unpack2(a11, az1, aw1);
    float inv = 1.0f / fmaxf(den, 1e-9f);
    __half2 o01 = __floats2half2_rn((ax0 + ax1) * inv, (ay0 + ay1) * inv);
    __half2 o23 = __floats2half2_rn((az0 + az1) * inv, (aw0 + aw1) * inv);
    uint2 st;
    st.x = *reinterpret_cast<unsigned int*>(&o01);
    st.y = *reinterpret_cast<unsigned int*>(&o23);
    ((uint2*)g_out_h)[(size_t)w * 32 + lane] = st;
}

// ============================================================
// K5: semantic attention scores (round-10 4-row form; fp16 in)
// ============================================================
__global__ void sem_kernel(const float* __restrict__ bias,
                           const float* __restrict__ sem_w1,
                           const float* __restrict__ sem_b1,
                           const float* __restrict__ sem_w2) {
    __shared__ __align__(16) float z_sh[32 * HF];
    int p = blockIdx.y;
    int base = blockIdx.x * 32;

    for (int i = threadIdx.x; i < 32 * HF; i += 256) {
        int node = base + (i >> 7);
        int c = i & 127;
        float z = 0.f;
        if (node < Nn) {
            float raw = __half2float(g_out_h[((size_t)p * Nn + node) * HF + c])
                        + bias[(size_t)p * HF + c];
            z = raw > 0.f ? raw : (__expf(raw) - 1.0f);
        }
        z_sh[i] = z;
    }
    __syncthreads();

    int warpId = threadIdx.x >> 5;
    int lane = threadIdx.x & 31;
    const ulonglong2* W2 = (const ulonglong2*)sem_w1;
    const float4* z4 = (const float4*)z_sh;

    unsigned long long acc[4][2];
    #pragma unroll
    for (int r = 0; r < 4; r++) { acc[r][0] = 0ull; acc[r][1] = 0ull; }

    for (int k4 = 0; k4 < 32; k4++) {
        float4 zv0 = z4[(warpId * 4 + 0) * 32 + k4];
        float4 zv1 = z4[(warpId * 4 + 1) * 32 + k4];
        float4 zv2 = z4[(warpId * 4 + 2) * 32 + k4];
        float4 zv3 = z4[(warpId * 4 + 3) * 32 + k4];
        float z0v[4] = {zv0.x, zv0.y, zv0.z, zv0.w};
        float z1v[4] = {zv1.x, zv1.y, zv1.z, zv1.w};
        float z2v[4] = {zv2.x, zv2.y, zv2.z, zv2.w};
        float z3v[4] = {zv3.x, zv3.y, zv3.z, zv3.w};
        #pragma unroll
        for (int kk = 0; kk < 4; kk++) {
            ulonglong2 wv = W2[(size_t)(k4 * 4 + kk) * 32 + lane];
            unsigned long long p0 = pack2(z0v[kk], z0v[kk]);
            unsigned long long p1 = pack2(z1v[kk], z1v[kk]);
            unsigned long long p2 = pack2(z2v[kk], z2v[kk]);
            unsigned long long p3 = pack2(z3v[kk], z3v[kk]);
            acc[0][0] = fma2(p0, wv.x, acc[0][0]); acc[0][1] = fma2(p0, wv.y, acc[0][1]);
            acc[1][0] = fma2(p1, wv.x, acc[1][0]); acc[1][1] = fma2(p1, wv.y, acc[1][1]);
            acc[2][0] = fma2(p2, wv.x, acc[2][0]); acc[2][1] = fma2(p2, wv.y, acc[2][1]);
            acc[3][0] = fma2(p3, wv.x, acc[3][0]); acc[3][1] = fma2(p3, wv.y, acc[3][1]);
        }
    }

    float4 b14 = ((const float4*)sem_b1)[lane];
    float4 w24 = ((const float4*)sem_w2)[lane];

    float total = 0.f;
    #pragma unroll
    for (int j = 0; j < 4; j++) {
        float4 a;
        unpack2(acc[j][0], a.x, a.y);
        unpack2(acc[j][1], a.z, a.w);
        float cj = tanhf(a.x + b14.x) * w24.x
                 + tanhf(a.y + b14.y) * w24.y
                 + tanhf(a.z + b14.z) * w24.z
                 + tanhf(a.w + b14.w) * w24.w;
        #pragma unroll
        for (int off = 16; off >= 1; off >>= 1)
            cj += __shfl_xor_sync(0xffffffffu, cj, off);
        int node = base + warpId * 4 + j;
        if (node < Nn) total += cj;
    }
    if (lane == 0) atomicAdd(&g_wsum[p], total);
}

// ============================================================
// K6: combine with semantic softmax (fp16 in)
// ============================================================
__global__ void final_kernel(const float* __restrict__ bias,
                             float* __restrict__ out) {
    size_t i = (size_t)blockIdx.x * 256 + threadIdx.x;
    if (i >= (size_t)Nn * 32) return;
    float w0 = g_wsum[0] * (1.0f / Nn);
    float w1 = g_wsum[1] * (1.0f / Nn);
    float m = fmaxf(w0, w1);
    float e0 = __expf(w0 - m), e1 = __expf(w1 - m);
    float inv = 1.0f / (e0 + e1);
    float b0 = e0 * inv, b1 = e1 * inv;

    int c4 = (int)(i & 31);
    uint2 h0 = ((const uint2*)g_out_h)[i];
    uint2 h1 = ((const uint2*)g_out_h)[(size_t)Nn * 32 + i];
    float2 r0a = __half22float2(*reinterpret_cast<__half2*>(&h0.x));
    float2 r0b = __half22float2(*reinterpret_cast<__half2*>(&h0.y));
    float2 r1a = __half22float2(*reinterpret_cast<__half2*>(&h1.x));
    float2 r1b = __half22float2(*reinterpret_cast<__half2*>(&h1.y));
    float4 bi0 = ((const float4*)bias)[c4];
    float4 bi1 = ((const float4*)bias)[32 + c4];

    float4 res;
    float v;
    v = r0a.x + bi0.x; v = v > 0.f ? v : (__expf(v) - 1.f); res.x = b0 * v;
    v = r0a.y + bi0.y; v = v > 0.f ? v : (__expf(v) - 1.f); res.y = b0 * v;
    v = r0b.x + bi0.z; v = v > 0.f ? v : (__expf(v) - 1.f); res.z = b0 * v;
    v = r0b.y + bi0.w; v = v > 0.f ? v : (__expf(v) - 1.f); res.w = b0 * v;
    v = r1a.x + bi1.x; v = v > 0.f ? v : (__expf(v) - 1.f); res.x += b1 * v;
    v = r1a.y + bi1.y; v = v > 0.f ? v : (__expf(v) - 1.f); res.y += b1 * v;
    v = r1b.x + bi1.z; v = v > 0.f ? v : (__expf(v) - 1.f); res.z += b1 * v;
    v = r1b.y + bi1.w; v = v > 0.f ? v : (__expf(v) - 1.f); res.w += b1 * v;

    ((float4*)out)[i] = res;
}

extern "C" void kernel_launch(void* const* d_in, const int* in_sizes, int n_in,
                              void* d_out, int out_size) {
    const float* h      = (const float*)d_in[0];
    const int*   src    = (const int*)  d_in[1];
    const int*   dst    = (const int*)  d_in[2];
    const float* fc_w   = (const float*)d_in[3];
    const float* attn_l = (const float*)d_in[4];
    const float* attn_r = (const float*)d_in[5];
    const float* bias   = (const float*)d_in[6];
    const float* sem_w1 = (const float*)d_in[7];
    const float* sem_b1 = (const float*)d_in[8];
    const float* sem_w2 = (const float*)d_in[9];
    float* out = (float*)d_out;

    static cudaStream_t s2 = nullptr;
    static cudaEvent_t evFork = nullptr, evJoin = nullptr;
    if (s2 == nullptr) {
        cudaStreamCreateWithFlags(&s2, cudaStreamNonBlocking);
        cudaEventCreateWithFlags(&evFork, cudaEventDisableTiming);
        cudaEventCreateWithFlags(&evJoin, cudaEventDisableTiming);
    }

    void *p_deg, *p_wsum;
    cudaGetSymbolAddress(&p_deg, g_deg);
    cudaGetSymbolAddress(&p_wsum, g_wsum);

    // fork: full CSR build (hist+scan+scatter) on s2, feat GEMM on main
    cudaEventRecord(evFork, 0);
    cudaStreamWaitEvent(s2, evFork, 0);

    // --- branch B (s2): histogram + offsets + scatter ---
    cudaMemsetAsync(p_deg, 0, sizeof(int) * TOT, s2);
    dim3 gEdge((Ee + 255) / 256, Pp);
    hist_kernel<<<gEdge, 256, 0, s2>>>(dst);
    scan1_kernel<<<SCAN_B, 1024, 0, s2>>>();
    scan23_kernel<<<SCAN_B, 1024, 0, s2>>>();
    scatter_kernel<<<gEdge, 256, 0, s2>>>(src, dst);
    cudaEventRecord(evJoin, s2);

    // --- branch A (main): features + attn dots ---
    cudaMemsetAsync(p_wsum, 0, sizeof(float) * Pp);
    dim3 gFeat((Nn / 8 + 7) / 8, Pp);
    feat_kernel<<<gFeat, 256>>>(h, fc_w, attn_l, attn_r);

    // join: agg needs CSR (s2) and feat/el/er (main)
    cudaStreamWaitEvent(0, evJoin, 0);

    agg_kernel<<<(TOT + 7) / 8, 256>>>();

    dim3 gSem((Nn + 31) / 32, Pp);
    sem_kernel<<<gSem, 256>>>(bias, sem_w1, sem_b1, sem_w2);

    final_kernel<<<((size_t)Nn * 32 + 255) / 256, 256>>>(bias, out);
}